// round 8
// baseline (speedup 1.0000x reference)
#include <cuda_runtime.h>
#include <cuda_bf16.h>
#include <cstdint>

#define BSZ 4
#define CIN_ 256
#define CQK_ 128
#define NPT 4096
#define KT 32            // keys per tile
#define NT 128           // tiles
#define QT 64            // queries per CTA

// bf16 scratch (device globals; no allocation allowed)
__device__ __nv_bfloat16 g_qh[BSZ * NPT * CQK_];   // [b][n][o]
__device__ __nv_bfloat16 g_ql[BSZ * NPT * CQK_];
__device__ __nv_bfloat16 g_kh[BSZ * NPT * CQK_];   // [b][m][o]
__device__ __nv_bfloat16 g_kl[BSZ * NPT * CQK_];
__device__ __nv_bfloat16 g_vh[BSZ * CIN_ * NPT];   // [b][c][m] channel-major

// ================= helpers =================
typedef unsigned long long u64;

__device__ __forceinline__ u64 pack2(float lo, float hi) {
    u64 r; asm("mov.b64 %0, {%1, %2};" : "=l"(r) : "f"(lo), "f"(hi)); return r;
}
__device__ __forceinline__ void unpack2(u64 v, float& lo, float& hi) {
    asm("mov.b64 {%0, %1}, %2;" : "=f"(lo), "=f"(hi) : "l"(v));
}
__device__ __forceinline__ void ffma2(u64& d, u64 a, u64 b) {
    asm("fma.rn.f32x2 %0, %1, %2, %0;" : "+l"(d) : "l"(a), "l"(b));
}
__device__ __forceinline__ uint32_t smem_u32(const void* p) {
    uint32_t a;
    asm("{ .reg .u64 t; cvta.to.shared.u64 t, %1; cvt.u32.u64 %0, t; }" : "=r"(a) : "l"(p));
    return a;
}
__device__ __forceinline__ void cp_async16(uint32_t dst, const void* src) {
    asm volatile("cp.async.cg.shared.global [%0], [%1], 16;" :: "r"(dst), "l"(src) : "memory");
}
#define CP_COMMIT() asm volatile("cp.async.commit_group;" ::: "memory")
#define CP_WAIT0()  asm volatile("cp.async.wait_group 0;" ::: "memory")

__device__ __forceinline__ void ldsm4(uint32_t addr, uint32_t r[4]) {
    asm volatile("ldmatrix.sync.aligned.m8n8.x4.shared.b16 {%0,%1,%2,%3}, [%4];"
        : "=r"(r[0]), "=r"(r[1]), "=r"(r[2]), "=r"(r[3]) : "r"(addr));
}
__device__ __forceinline__ void mma16816(float c[4], const uint32_t a[4],
                                         uint32_t b0, uint32_t b1) {
    asm volatile("mma.sync.aligned.m16n8k16.row.col.f32.bf16.bf16.f32 "
        "{%0,%1,%2,%3}, {%4,%5,%6,%7}, {%8,%9}, {%0,%1,%2,%3};"
        : "+f"(c[0]), "+f"(c[1]), "+f"(c[2]), "+f"(c[3])
        : "r"(a[0]), "r"(a[1]), "r"(a[2]), "r"(a[3]), "r"(b0), "r"(b1));
}

// 256B-row swizzle (Q, K): conflict-free ldmatrix + cp.async
__device__ __forceinline__ uint32_t sw256(int r, int byte) {
    return (uint32_t)(r * 256 + (((byte >> 4) ^ (r & 7)) << 4) + (byte & 15));
}
// 64B-row swizzle (V, P): banks = 16(r&1)+4(chunk^((r>>1)&3)) -> distinct over 8 rows
__device__ __forceinline__ uint32_t sw64(int r, int byte) {
    return (uint32_t)(r * 64 + (((byte >> 4) ^ ((r >> 1) & 3)) << 4) + (byte & 15));
}

// ================= Projection GEMM (FFMA fp32, bf16 split outputs) =================
template<int DST>
__global__ __launch_bounds__(256)
void proj_kernel(const float* __restrict__ W, const float* __restrict__ bias,
                 const float* __restrict__ X)
{
    __shared__ float sX[32 * 64];
    __shared__ float sW[32 * 68];

    const int tid = threadIdx.x;
    const int tn = tid >> 4, to = tid & 15;
    const int b  = blockIdx.z;
    const int n0 = blockIdx.x * 64;
    const int o0 = blockIdx.y * 64;
    const float* Xb = X + (size_t)b * CIN_ * NPT;

    u64 acc[4][2];
#pragma unroll
    for (int i = 0; i < 4; i++) { acc[i][0] = 0ull; acc[i][1] = 0ull; }

    for (int ct = 0; ct < CIN_; ct += 32) {
#pragma unroll
        for (int r = 0; r < 8; r++) {
            int idx = tid + r * 256;
            int c = idx >> 6, n = idx & 63;
            sX[c * 64 + n] = Xb[(size_t)(ct + c) * NPT + n0 + n];
        }
#pragma unroll
        for (int r = 0; r < 8; r++) {
            int idx = tid + r * 256;
            int o = idx >> 5, c = idx & 31;
            sW[c * 68 + o] = W[(size_t)(o0 + o) * CIN_ + ct + c];
        }
        __syncthreads();
#pragma unroll 8
        for (int c = 0; c < 32; c++) {
            float4 xf = *(const float4*)&sX[c * 64 + 4 * tn];
            ulonglong2 wf = *(const ulonglong2*)&sW[c * 68 + 4 * to];
            u64 x0 = pack2(xf.x, xf.x), x1 = pack2(xf.y, xf.y);
            u64 x2 = pack2(xf.z, xf.z), x3 = pack2(xf.w, xf.w);
            ffma2(acc[0][0], x0, wf.x); ffma2(acc[0][1], x0, wf.y);
            ffma2(acc[1][0], x1, wf.x); ffma2(acc[1][1], x1, wf.y);
            ffma2(acc[2][0], x2, wf.x); ffma2(acc[2][1], x2, wf.y);
            ffma2(acc[3][0], x3, wf.x); ffma2(acc[3][1], x3, wf.y);
        }
        __syncthreads();
    }

    float4 bv4 = *(const float4*)&bias[o0 + 4 * to];
    float v[4][4];
#pragma unroll
    for (int i = 0; i < 4; i++) {
        unpack2(acc[i][0], v[i][0], v[i][1]); unpack2(acc[i][1], v[i][2], v[i][3]);
        v[i][0] += bv4.x; v[i][1] += bv4.y; v[i][2] += bv4.z; v[i][3] += bv4.w;
    }

    if (DST < 2) {
        __nv_bfloat16* oh = (DST == 0) ? g_qh : g_kh;
        __nv_bfloat16* ol = (DST == 0) ? g_ql : g_kl;
#pragma unroll
        for (int i = 0; i < 4; i++) {
            uint32_t hp[2], lp[2];
#pragma unroll
            for (int half = 0; half < 2; half++) {
                __nv_bfloat16 h0 = __float2bfloat16_rn(v[i][2*half]);
                __nv_bfloat16 h1 = __float2bfloat16_rn(v[i][2*half+1]);
                __nv_bfloat16 l0 = __float2bfloat16_rn(v[i][2*half]   - __bfloat162float(h0));
                __nv_bfloat16 l1 = __float2bfloat16_rn(v[i][2*half+1] - __bfloat162float(h1));
                hp[half] = (uint32_t)__bfloat16_as_ushort(h0) | ((uint32_t)__bfloat16_as_ushort(h1) << 16);
                lp[half] = (uint32_t)__bfloat16_as_ushort(l0) | ((uint32_t)__bfloat16_as_ushort(l1) << 16);
            }
            size_t idx = (size_t)(b * NPT + n0 + 4 * tn + i) * CQK_ + o0 + 4 * to;
            *(uint2*)&oh[idx] = make_uint2(hp[0], hp[1]);
            *(uint2*)&ol[idx] = make_uint2(lp[0], lp[1]);
        }
    } else {
#pragma unroll
        for (int j = 0; j < 4; j++) {
            uint32_t p0 = (uint32_t)__bfloat16_as_ushort(__float2bfloat16_rn(v[0][j])) |
                          ((uint32_t)__bfloat16_as_ushort(__float2bfloat16_rn(v[1][j])) << 16);
            uint32_t p1 = (uint32_t)__bfloat16_as_ushort(__float2bfloat16_rn(v[2][j])) |
                          ((uint32_t)__bfloat16_as_ushort(__float2bfloat16_rn(v[3][j])) << 16);
            size_t idx = (size_t)(b * CIN_ + o0 + 4 * to + j) * NPT + n0 + 4 * tn;
            *(uint2*)&g_vh[idx] = make_uint2(p0, p1);
        }
    }
}

// ================= Fused mma.sync flash attention (2 CTAs/SM) =================
// SMEM layout (bytes):
#define SM_QH   0u
#define SM_QL   16384u
#define SM_ST0  32768u       // stage: { Kh 8K | Kl 8K | V 16K } = 32K, x2
#define STAGESZ 32768u
#define SM_P    98304u       // P bf16 [64][32] (64B rows, sw64)
#define SM_MAX  102400u      // [64][2] f32
#define SM_L    102912u      // [64][2] f32
#define SMEM_TOTAL 103424

__device__ __forceinline__ void load_stage(uint32_t sb, int stage, int m0, int tid,
    const __nv_bfloat16* kh, const __nv_bfloat16* kl, const __nv_bfloat16* vh)
{
    uint32_t stg = sb + SM_ST0 + (uint32_t)stage * STAGESZ;
#pragma unroll
    for (int i = 0; i < 8; i++) {
        int c = tid + i * 256;
        if (c < 1024) {                              // Kh / Kl : 32 rows x 256B
            int cc = c & 511;
            int r = cc >> 4, ch = cc & 15;
            const __nv_bfloat16* src = ((c < 512) ? kh : kl) + (size_t)(m0 + r) * CQK_ + ch * 8;
            cp_async16(stg + ((c < 512) ? 0u : 8192u) + sw256(r, ch * 16), src);
        } else {                                     // V : 256 ch x 64B
            int cc = c - 1024;
            int r = cc >> 2, ch = cc & 3;
            const __nv_bfloat16* src = vh + (size_t)r * NPT + m0 + ch * 8;
            cp_async16(stg + 16384u + sw64(r, ch * 16), src);
        }
    }
}

extern __shared__ __align__(16) char smem[];

__global__ __launch_bounds__(256, 2)
void attn_tc(const float* __restrict__ gin, const float* __restrict__ gamma_p,
             float* __restrict__ out)
{
    const uint32_t sb = smem_u32(smem);
    const int tid  = threadIdx.x;
    const int lane = tid & 31, wid = tid >> 5;
    const int wq = wid & 3, wh = wid >> 2;     // query group / half (keys in S, chans in PV)
    const int g = lane >> 2, tig = lane & 3;
    const int r0 = 16 * wq;
    const int b  = blockIdx.y;
    const int n0 = blockIdx.x * QT;

    const __nv_bfloat16* qh = g_qh + (size_t)(b * NPT + n0) * CQK_;
    const __nv_bfloat16* ql = g_ql + (size_t)(b * NPT + n0) * CQK_;
    const __nv_bfloat16* kh = g_kh + (size_t)b * NPT * CQK_;
    const __nv_bfloat16* kl = g_kl + (size_t)b * NPT * CQK_;
    const __nv_bfloat16* vh = g_vh + (size_t)b * CIN_ * NPT;

    // prologue: Q (hi+lo, 64 rows x 256B each) + stage0
#pragma unroll
    for (int i = 0; i < 8; i++) {
        int c = tid + i * 256;
        int cc = c & 1023;
        int r = cc >> 4, ch = cc & 15;
        const __nv_bfloat16* src = ((c < 1024) ? qh : ql) + (size_t)r * CQK_ + ch * 8;
        cp_async16(sb + ((c < 1024) ? SM_QH : SM_QL) + sw256(r, ch * 16), src);
    }
    load_stage(sb, 0, 0, tid, kh, kl, vh);
    CP_COMMIT();

    float accO[16][4];
#pragma unroll
    for (int j = 0; j < 16; j++)
#pragma unroll
        for (int q = 0; q < 4; q++) accO[j][q] = 0.0f;

    float lsum0 = 0.0f, lsum1 = 0.0f;
    float m0r = 0.0f, m1r = 0.0f;
    const int n0w = 16 * wh;                   // warp's key sub-range in S

    for (int t = 0; t < NT; t++) {
        CP_WAIT0();
        __syncthreads();
        if (t + 1 < NT) { load_stage(sb, (t + 1) & 1, (t + 1) * KT, tid, kh, kl, vh); CP_COMMIT(); }

        const uint32_t stg = sb + SM_ST0 + (uint32_t)(t & 1) * STAGESZ;
        const uint32_t sKh = stg, sKl = stg + 8192u, sV = stg + 16384u;

        // ---- S = Qh·Kh + Ql·Kh + Qh·Kl  (16 rows x 16 keys per warp) ----
        float accS[2][4];
#pragma unroll
        for (int j = 0; j < 2; j++)
#pragma unroll
            for (int q = 0; q < 4; q++) accS[j][q] = 0.0f;

#pragma unroll
        for (int kk = 0; kk < 8; kk++) {
            uint32_t Ah[4], Al[4], Bh[4], Bl[4];
            {
                int rr = r0 + (lane & 15);
                int byte = kk * 32 + ((lane >> 4) & 1) * 16;
                ldsm4(sb + SM_QH + sw256(rr, byte), Ah);
                ldsm4(sb + SM_QL + sw256(rr, byte), Al);
            }
            {
                int rr = n0w + ((lane >> 4) << 3) + (lane & 7);
                int byte = kk * 32 + ((lane >> 3) & 1) * 16;
                ldsm4(sKh + sw256(rr, byte), Bh);
                ldsm4(sKl + sw256(rr, byte), Bl);
            }
            mma16816(accS[0], Ah, Bh[0], Bh[1]);
            mma16816(accS[1], Ah, Bh[2], Bh[3]);
            mma16816(accS[0], Al, Bh[0], Bh[1]);
            mma16816(accS[1], Al, Bh[2], Bh[3]);
            mma16816(accS[0], Ah, Bl[0], Bl[1]);
            mma16816(accS[1], Ah, Bl[2], Bl[3]);
        }

        // ---- fixed row max from tile 0 ----
        if (t == 0) {
            float mA = fmaxf(fmaxf(accS[0][0], accS[0][1]), fmaxf(accS[1][0], accS[1][1]));
            float mB = fmaxf(fmaxf(accS[0][2], accS[0][3]), fmaxf(accS[1][2], accS[1][3]));
            mA = fmaxf(mA, __shfl_xor_sync(0xffffffffu, mA, 1));
            mA = fmaxf(mA, __shfl_xor_sync(0xffffffffu, mA, 2));
            mB = fmaxf(mB, __shfl_xor_sync(0xffffffffu, mB, 1));
            mB = fmaxf(mB, __shfl_xor_sync(0xffffffffu, mB, 2));
            float* sM = (float*)(smem + SM_MAX);
            if (tig == 0) {
                sM[(r0 + g) * 2 + wh]     = mA;
                sM[(r0 + g + 8) * 2 + wh] = mB;
            }
            __syncthreads();
            m0r = fmaxf(sM[(r0 + g) * 2],     sM[(r0 + g) * 2 + 1]);
            m1r = fmaxf(sM[(r0 + g + 8) * 2], sM[(r0 + g + 8) * 2 + 1]);
        }

        // ---- softmax + P(bf16) to smem, l from rounded P ----
#pragma unroll
        for (int j = 0; j < 2; j++) {
            float e0 = __expf(accS[j][0] - m0r);
            float e1 = __expf(accS[j][1] - m0r);
            float e2 = __expf(accS[j][2] - m1r);
            float e3 = __expf(accS[j][3] - m1r);
            __nv_bfloat162 p01 = __floats2bfloat162_rn(e0, e1);
            __nv_bfloat162 p23 = __floats2bfloat162_rn(e2, e3);
            lsum0 += __bfloat162float(p01.x) + __bfloat162float(p01.y);
            lsum1 += __bfloat162float(p23.x) + __bfloat162float(p23.y);
            int kb = (n0w + 8 * j + 2 * tig) * 2;
            *(uint32_t*)(smem + SM_P + sw64(r0 + g,     kb)) = *(uint32_t*)&p01;
            *(uint32_t*)(smem + SM_P + sw64(r0 + g + 8, kb)) = *(uint32_t*)&p23;
        }
        __syncthreads();

        // ---- O += P · V  (warp: 16 rows x 128 channels) ----
#pragma unroll
        for (int kk = 0; kk < 2; kk++) {
            uint32_t Ap[4];
            {
                int rr = r0 + (lane & 15);
                int byte = kk * 32 + ((lane >> 4) & 1) * 16;
                ldsm4(sb + SM_P + sw64(rr, byte), Ap);
            }
#pragma unroll
            for (int jp = 0; jp < 8; jp++) {
                int rr = 128 * wh + 16 * jp + ((lane >> 4) << 3) + (lane & 7);
                int byte = kk * 32 + ((lane >> 3) & 1) * 16;
                uint32_t Bv[4];
                ldsm4(sV + sw64(rr, byte), Bv);
                mma16816(accO[2*jp],   Ap, Bv[0], Bv[1]);
                mma16816(accO[2*jp+1], Ap, Bv[2], Bv[3]);
            }
        }
    }

    // ---- l reduction ----
    lsum0 += __shfl_xor_sync(0xffffffffu, lsum0, 1);
    lsum0 += __shfl_xor_sync(0xffffffffu, lsum0, 2);
    lsum1 += __shfl_xor_sync(0xffffffffu, lsum1, 1);
    lsum1 += __shfl_xor_sync(0xffffffffu, lsum1, 2);
    float* sL = (float*)(smem + SM_L);
    if (tig == 0) {
        sL[(r0 + g) * 2 + wh]     = lsum0;
        sL[(r0 + g + 8) * 2 + wh] = lsum1;
    }
    __syncthreads();
    const float rl0 = 1.0f / (sL[(r0 + g) * 2]     + sL[(r0 + g) * 2 + 1]);
    const float rl1 = 1.0f / (sL[(r0 + g + 8) * 2] + sL[(r0 + g + 8) * 2 + 1]);
    const float gam = gamma_p[0];

    // ---- epilogue: smem transpose, coalesced  out = gamma*O/l + g ----
    float* sT = (float*)(smem + SM_ST0);       // [64 ch][64 q] pad-68
#pragma unroll 1
    for (int blk = 0; blk < 4; blk++) {
        if (wh == (blk >> 1)) {
#pragma unroll
            for (int jj = 0; jj < 8; jj++) {
                int j  = 8 * (blk & 1) + jj;
                int cl = 8 * jj + 2 * tig;
                sT[(cl    ) * 68 + r0 + g]     = gam * accO[j][0] * rl0;
                sT[(cl + 1) * 68 + r0 + g]     = gam * accO[j][1] * rl0;
                sT[(cl    ) * 68 + r0 + g + 8] = gam * accO[j][2] * rl1;
                sT[(cl + 1) * 68 + r0 + g + 8] = gam * accO[j][3] * rl1;
            }
        }
        __syncthreads();
#pragma unroll
        for (int it = 0; it < 16; it++) {
            int idx = tid + it * 256;
            int q = idx & 63, cl = idx >> 6;
            size_t gi = (size_t)(b * CIN_ + 64 * blk + cl) * NPT + n0 + q;
            out[gi] = sT[cl * 68 + q] + gin[gi];
        }
        __syncthreads();
    }
}

// ================= launch =================
extern "C" void kernel_launch(void* const* d_in, const int* in_sizes, int n_in,
                              void* d_out, int out_size)
{
    const float* x     = (const float*)d_in[0];
    const float* g     = (const float*)d_in[1];
    const float* Wq    = (const float*)d_in[2];
    const float* bq    = (const float*)d_in[3];
    const float* Wk    = (const float*)d_in[4];
    const float* bk    = (const float*)d_in[5];
    const float* Wv    = (const float*)d_in[6];
    const float* bv    = (const float*)d_in[7];
    const float* gamma = (const float*)d_in[8];
    float* out = (float*)d_out;
    (void)in_sizes; (void)n_in; (void)out_size;

    cudaFuncSetAttribute(attn_tc, cudaFuncAttributeMaxDynamicSharedMemorySize, SMEM_TOTAL);

    proj_kernel<0><<<dim3(NPT / 64, CQK_ / 64, BSZ), 256>>>(Wq, bq, x);
    proj_kernel<1><<<dim3(NPT / 64, CQK_ / 64, BSZ), 256>>>(Wk, bk, g);
    proj_kernel<2><<<dim3(NPT / 64, CIN_ / 64, BSZ), 256>>>(Wv, bv, g);

    attn_tc<<<dim3(NPT / QT, BSZ), 256, SMEM_TOTAL>>>(g, gamma, out);
}

// round 9
// speedup vs baseline: 1.9935x; 1.9935x over previous
#include <cuda_runtime.h>
#include <cuda_bf16.h>
#include <cstdint>

#define BSZ 4
#define CIN_ 256
#define CQK_ 128
#define NPT 4096
#define KT 64            // keys per tile
#define NT 64            // tiles
#define QT 128           // queries per CTA

// bf16 scratch (device globals; no allocation allowed)
__device__ __nv_bfloat16 g_qh[BSZ * NPT * CQK_];   // [b][n][o]
__device__ __nv_bfloat16 g_ql[BSZ * NPT * CQK_];
__device__ __nv_bfloat16 g_kh[BSZ * NPT * CQK_];   // [b][m][o]
__device__ __nv_bfloat16 g_kl[BSZ * NPT * CQK_];
__device__ __nv_bfloat16 g_vh[BSZ * CIN_ * NPT];   // [b][c][m] channel-major

// ================= helpers =================
typedef unsigned long long u64;

__device__ __forceinline__ u64 pack2(float lo, float hi) {
    u64 r; asm("mov.b64 %0, {%1, %2};" : "=l"(r) : "f"(lo), "f"(hi)); return r;
}
__device__ __forceinline__ void unpack2(u64 v, float& lo, float& hi) {
    asm("mov.b64 {%0, %1}, %2;" : "=f"(lo), "=f"(hi) : "l"(v));
}
__device__ __forceinline__ void ffma2(u64& d, u64 a, u64 b) {
    asm("fma.rn.f32x2 %0, %1, %2, %0;" : "+l"(d) : "l"(a), "l"(b));
}
__device__ __forceinline__ uint32_t smem_u32(const void* p) {
    uint32_t a;
    asm("{ .reg .u64 t; cvta.to.shared.u64 t, %1; cvt.u32.u64 %0, t; }" : "=r"(a) : "l"(p));
    return a;
}
__device__ __forceinline__ void cp_async16(uint32_t dst, const void* src) {
    asm volatile("cp.async.cg.shared.global [%0], [%1], 16;" :: "r"(dst), "l"(src) : "memory");
}
#define CP_COMMIT() asm volatile("cp.async.commit_group;" ::: "memory")
#define CP_WAIT0()  asm volatile("cp.async.wait_group 0;" ::: "memory")

__device__ __forceinline__ void ldsm4(uint32_t addr, uint32_t r[4]) {
    asm volatile("ldmatrix.sync.aligned.m8n8.x4.shared.b16 {%0,%1,%2,%3}, [%4];"
        : "=r"(r[0]), "=r"(r[1]), "=r"(r[2]), "=r"(r[3]) : "r"(addr));
}
__device__ __forceinline__ void mma16816(float c[4], const uint32_t a[4],
                                         uint32_t b0, uint32_t b1) {
    asm volatile("mma.sync.aligned.m16n8k16.row.col.f32.bf16.bf16.f32 "
        "{%0,%1,%2,%3}, {%4,%5,%6,%7}, {%8,%9}, {%0,%1,%2,%3};"
        : "+f"(c[0]), "+f"(c[1]), "+f"(c[2]), "+f"(c[3])
        : "r"(a[0]), "r"(a[1]), "r"(a[2]), "r"(a[3]), "r"(b0), "r"(b1));
}

// 256B-row swizzle (Q, K): conflict-free ldmatrix + cp.async
__device__ __forceinline__ uint32_t sw256(int r, int byte) {
    return (uint32_t)(r * 256 + (((byte >> 4) ^ (r & 7)) << 4) + (byte & 15));
}
// 128B-row swizzle (V): conflict-free
__device__ __forceinline__ uint32_t sw128(int r, int byte) {
    return (uint32_t)(r * 128 + (((byte >> 4) ^ (r & 7)) << 4) + (byte & 15));
}

// ================= Projection GEMM (FFMA fp32, bf16 split outputs) =================
template<int DST>
__global__ __launch_bounds__(256)
void proj_kernel(const float* __restrict__ W, const float* __restrict__ bias,
                 const float* __restrict__ X)
{
    __shared__ float sX[32 * 64];
    __shared__ float sW[32 * 68];

    const int tid = threadIdx.x;
    const int tn = tid >> 4, to = tid & 15;
    const int b  = blockIdx.z;
    const int n0 = blockIdx.x * 64;
    const int o0 = blockIdx.y * 64;
    const float* Xb = X + (size_t)b * CIN_ * NPT;

    u64 acc[4][2];
#pragma unroll
    for (int i = 0; i < 4; i++) { acc[i][0] = 0ull; acc[i][1] = 0ull; }

    for (int ct = 0; ct < CIN_; ct += 32) {
#pragma unroll
        for (int r = 0; r < 8; r++) {
            int idx = tid + r * 256;
            int c = idx >> 6, n = idx & 63;
            sX[c * 64 + n] = Xb[(size_t)(ct + c) * NPT + n0 + n];
        }
#pragma unroll
        for (int r = 0; r < 8; r++) {
            int idx = tid + r * 256;
            int o = idx >> 5, c = idx & 31;
            sW[c * 68 + o] = W[(size_t)(o0 + o) * CIN_ + ct + c];
        }
        __syncthreads();
#pragma unroll 8
        for (int c = 0; c < 32; c++) {
            float4 xf = *(const float4*)&sX[c * 64 + 4 * tn];
            ulonglong2 wf = *(const ulonglong2*)&sW[c * 68 + 4 * to];
            u64 x0 = pack2(xf.x, xf.x), x1 = pack2(xf.y, xf.y);
            u64 x2 = pack2(xf.z, xf.z), x3 = pack2(xf.w, xf.w);
            ffma2(acc[0][0], x0, wf.x); ffma2(acc[0][1], x0, wf.y);
            ffma2(acc[1][0], x1, wf.x); ffma2(acc[1][1], x1, wf.y);
            ffma2(acc[2][0], x2, wf.x); ffma2(acc[2][1], x2, wf.y);
            ffma2(acc[3][0], x3, wf.x); ffma2(acc[3][1], x3, wf.y);
        }
        __syncthreads();
    }

    float4 bv4 = *(const float4*)&bias[o0 + 4 * to];
    float v[4][4];
#pragma unroll
    for (int i = 0; i < 4; i++) {
        unpack2(acc[i][0], v[i][0], v[i][1]); unpack2(acc[i][1], v[i][2], v[i][3]);
        v[i][0] += bv4.x; v[i][1] += bv4.y; v[i][2] += bv4.z; v[i][3] += bv4.w;
    }

    if (DST < 2) {
        __nv_bfloat16* oh = (DST == 0) ? g_qh : g_kh;
        __nv_bfloat16* ol = (DST == 0) ? g_ql : g_kl;
#pragma unroll
        for (int i = 0; i < 4; i++) {
            uint32_t hp[2], lp[2];
#pragma unroll
            for (int half = 0; half < 2; half++) {
                __nv_bfloat16 h0 = __float2bfloat16_rn(v[i][2*half]);
                __nv_bfloat16 h1 = __float2bfloat16_rn(v[i][2*half+1]);
                __nv_bfloat16 l0 = __float2bfloat16_rn(v[i][2*half]   - __bfloat162float(h0));
                __nv_bfloat16 l1 = __float2bfloat16_rn(v[i][2*half+1] - __bfloat162float(h1));
                hp[half] = (uint32_t)__bfloat16_as_ushort(h0) | ((uint32_t)__bfloat16_as_ushort(h1) << 16);
                lp[half] = (uint32_t)__bfloat16_as_ushort(l0) | ((uint32_t)__bfloat16_as_ushort(l1) << 16);
            }
            size_t idx = (size_t)(b * NPT + n0 + 4 * tn + i) * CQK_ + o0 + 4 * to;
            *(uint2*)&oh[idx] = make_uint2(hp[0], hp[1]);
            *(uint2*)&ol[idx] = make_uint2(lp[0], lp[1]);
        }
    } else {
#pragma unroll
        for (int j = 0; j < 4; j++) {
            uint32_t p0 = (uint32_t)__bfloat16_as_ushort(__float2bfloat16_rn(v[0][j])) |
                          ((uint32_t)__bfloat16_as_ushort(__float2bfloat16_rn(v[1][j])) << 16);
            uint32_t p1 = (uint32_t)__bfloat16_as_ushort(__float2bfloat16_rn(v[2][j])) |
                          ((uint32_t)__bfloat16_as_ushort(__float2bfloat16_rn(v[3][j])) << 16);
            size_t idx = (size_t)(b * CIN_ + o0 + 4 * to + j) * NPT + n0 + 4 * tn;
            *(uint2*)&g_vh[idx] = make_uint2(p0, p1);
        }
    }
}

// ================= Fused mma.sync flash attention (P-in-registers) =================
// SMEM layout (bytes):
#define SM_QH   0u
#define SM_QL   32768u
#define SM_ST0  65536u       // stage: { Kh 16K | Kl 16K | V 32K } = 64K, x2
#define STAGESZ 65536u
#define SM_P    196608u      // per-warp P fragment regions: 16 x 1KB
#define SM_MAX  212992u      // [128][2] f32
#define SM_L    214016u      // [128][2] f32
#define SMEM_TOTAL 215040

__device__ __forceinline__ void load_stage(uint32_t sb, int stage, int m0, int tid,
    const __nv_bfloat16* kh, const __nv_bfloat16* kl, const __nv_bfloat16* vh)
{
    uint32_t stg = sb + SM_ST0 + (uint32_t)stage * STAGESZ;
#pragma unroll
    for (int i = 0; i < 8; i++) {
        int c = tid + i * 512;
        if (c < 2048) {
            int cc = c & 1023;
            int r = cc >> 4, ch = cc & 15;
            const __nv_bfloat16* src = ((c < 1024) ? kh : kl) + (size_t)(m0 + r) * CQK_ + ch * 8;
            cp_async16(stg + ((c < 1024) ? 0u : 16384u) + sw256(r, ch * 16), src);
        } else {
            int cc = c - 2048;
            int r = cc >> 3, ch = cc & 7;            // r = channel
            const __nv_bfloat16* src = vh + (size_t)r * NPT + m0 + ch * 8;
            cp_async16(stg + 32768u + sw128(r, ch * 16), src);
        }
    }
}

extern __shared__ __align__(16) char smem[];

__global__ __launch_bounds__(512, 1)
void attn_tc(const float* __restrict__ gin, const float* __restrict__ gamma_p,
             float* __restrict__ out)
{
    const uint32_t sb = smem_u32(smem);
    const int tid  = threadIdx.x;
    const int lane = tid & 31, wid = tid >> 5;
    const int wq = wid & 7, wh = wid >> 3;     // query group / half (keys in S, chans in PV)
    const int g = lane >> 2, tig = lane & 3;
    const int r0 = 16 * wq;
    const int b  = blockIdx.y;
    const int n0 = blockIdx.x * QT;

    const __nv_bfloat16* qh = g_qh + (size_t)(b * NPT + n0) * CQK_;
    const __nv_bfloat16* ql = g_ql + (size_t)(b * NPT + n0) * CQK_;
    const __nv_bfloat16* kh = g_kh + (size_t)b * NPT * CQK_;
    const __nv_bfloat16* kl = g_kl + (size_t)b * NPT * CQK_;
    const __nv_bfloat16* vh = g_vh + (size_t)b * CIN_ * NPT;

    // P fragment exchange regions (1KB per warp): [i 0..7][lane] u32
    const uint32_t pOwn  = sb + SM_P + (uint32_t)((wq * 2 + wh) * 1024) + (uint32_t)(lane * 4);
    const uint32_t pPeer = sb + SM_P + (uint32_t)((wq * 2 + (1 - wh)) * 1024) + (uint32_t)(lane * 4);

    // prologue: Q (hi+lo) + stage0
#pragma unroll
    for (int i = 0; i < 8; i++) {
        int c = tid + i * 512;
        int cc = c & 2047;
        int r = cc >> 4, ch = cc & 15;
        const __nv_bfloat16* src = ((c < 2048) ? qh : ql) + (size_t)r * CQK_ + ch * 8;
        cp_async16(sb + ((c < 2048) ? SM_QH : SM_QL) + sw256(r, ch * 16), src);
    }
    load_stage(sb, 0, 0, tid, kh, kl, vh);
    CP_COMMIT();

    float accO[16][4];
#pragma unroll
    for (int j = 0; j < 16; j++)
#pragma unroll
        for (int q = 0; q < 4; q++) accO[j][q] = 0.0f;

    float lsum0 = 0.0f, lsum1 = 0.0f;
    float m0r = 0.0f, m1r = 0.0f;
    const int n0w = 32 * wh;

    for (int t = 0; t < NT; t++) {
        CP_WAIT0();
        __syncthreads();            // the ONLY full-CTA barrier per tile
        if (t + 1 < NT) { load_stage(sb, (t + 1) & 1, (t + 1) * KT, tid, kh, kl, vh); CP_COMMIT(); }

        const uint32_t stg = sb + SM_ST0 + (uint32_t)(t & 1) * STAGESZ;
        const uint32_t sKh = stg, sKl = stg + 16384u, sV = stg + 32768u;

        // ---- S = Qh·Kh + Ql·Kh + Qh·Kl  (16 rows x 32 keys per warp) ----
        float accS[4][4];
#pragma unroll
        for (int j = 0; j < 4; j++)
#pragma unroll
            for (int q = 0; q < 4; q++) accS[j][q] = 0.0f;

#pragma unroll
        for (int kk = 0; kk < 8; kk++) {
            uint32_t Ah[4], Al[4];
            {
                int rr = r0 + (lane & 15);
                int byte = kk * 32 + ((lane >> 4) & 1) * 16;
                ldsm4(sb + SM_QH + sw256(rr, byte), Ah);
                ldsm4(sb + SM_QL + sw256(rr, byte), Al);
            }
#pragma unroll
            for (int jp = 0; jp < 2; jp++) {
                int rr = n0w + 16 * jp + ((lane >> 4) << 3) + (lane & 7);
                int byte = kk * 32 + ((lane >> 3) & 1) * 16;
                uint32_t Bh[4], Bl[4];
                ldsm4(sKh + sw256(rr, byte), Bh);
                ldsm4(sKl + sw256(rr, byte), Bl);
                mma16816(accS[2*jp],   Ah, Bh[0], Bh[1]);
                mma16816(accS[2*jp+1], Ah, Bh[2], Bh[3]);
                mma16816(accS[2*jp],   Al, Bh[0], Bh[1]);
                mma16816(accS[2*jp+1], Al, Bh[2], Bh[3]);
                mma16816(accS[2*jp],   Ah, Bl[0], Bl[1]);
                mma16816(accS[2*jp+1], Ah, Bl[2], Bl[3]);
            }
        }

        // ---- fixed row max from tile 0 ----
        if (t == 0) {
            float mA = fmaxf(fmaxf(accS[0][0], accS[0][1]), fmaxf(accS[1][0], accS[1][1]));
            mA = fmaxf(mA, fmaxf(fmaxf(accS[2][0], accS[2][1]), fmaxf(accS[3][0], accS[3][1])));
            float mB = fmaxf(fmaxf(accS[0][2], accS[0][3]), fmaxf(accS[1][2], accS[1][3]));
            mB = fmaxf(mB, fmaxf(fmaxf(accS[2][2], accS[2][3]), fmaxf(accS[3][2], accS[3][3])));
            mA = fmaxf(mA, __shfl_xor_sync(0xffffffffu, mA, 1));
            mA = fmaxf(mA, __shfl_xor_sync(0xffffffffu, mA, 2));
            mB = fmaxf(mB, __shfl_xor_sync(0xffffffffu, mB, 1));
            mB = fmaxf(mB, __shfl_xor_sync(0xffffffffu, mB, 2));
            float* sM = (float*)(smem + SM_MAX);
            if (tig == 0) {
                sM[(r0 + g) * 2 + wh]     = mA;
                sM[(r0 + g + 8) * 2 + wh] = mB;
            }
            __syncthreads();
            m0r = fmaxf(sM[(r0 + g) * 2],     sM[(r0 + g) * 2 + 1]);
            m1r = fmaxf(sM[(r0 + g + 8) * 2], sM[(r0 + g + 8) * 2 + 1]);
        }

        // ---- softmax: accS -> bf16 A-fragments in registers; l from rounded P ----
        uint32_t aP[2][4];
#pragma unroll
        for (int j = 0; j < 4; j++) {
            float e0 = __expf(accS[j][0] - m0r);
            float e1 = __expf(accS[j][1] - m0r);
            float e2 = __expf(accS[j][2] - m1r);
            float e3 = __expf(accS[j][3] - m1r);
            __nv_bfloat162 p01 = __floats2bfloat162_rn(e0, e1);
            __nv_bfloat162 p23 = __floats2bfloat162_rn(e2, e3);
            lsum0 += __bfloat162float(p01.x) + __bfloat162float(p01.y);
            lsum1 += __bfloat162float(p23.x) + __bfloat162float(p23.y);
            aP[j >> 1][((j & 1) << 1)]     = *(uint32_t*)&p01;   // a0/a2: row g
            aP[j >> 1][((j & 1) << 1) | 1] = *(uint32_t*)&p23;   // a1/a3: row g+8
        }

        // store own fragments for partner (SoA: conflict-free)
#pragma unroll
        for (int i = 0; i < 8; i++)
            *(uint32_t*)(smem + (pOwn - sb) + (uint32_t)(i * 128)) = aP[i >> 2][i & 3];

        // ---- PV own key-chunks first (hide partner skew under mma) ----
#pragma unroll
        for (int cc = 0; cc < 2; cc++) {
            const int kk = 2 * wh + cc;                 // global k16 chunk
#pragma unroll
            for (int jp = 0; jp < 8; jp++) {
                int rr = 128 * wh + 16 * jp + ((lane >> 4) << 3) + (lane & 7);
                int byte = kk * 32 + ((lane >> 3) & 1) * 16;
                uint32_t Bv[4];
                ldsm4(sV + sw128(rr, byte), Bv);
                mma16816(accO[2*jp],   aP[cc], Bv[0], Bv[1]);
                mma16816(accO[2*jp+1], aP[cc], Bv[2], Bv[3]);
            }
        }

        // pair barrier: partner's fragments visible
        asm volatile("bar.sync %0, %1;" :: "r"(1 + wq), "r"(64) : "memory");

        uint32_t aQ[2][4];
#pragma unroll
        for (int i = 0; i < 8; i++)
            aQ[i >> 2][i & 3] = *(const uint32_t*)(smem + (pPeer - sb) + (uint32_t)(i * 128));

        // ---- PV partner key-chunks ----
#pragma unroll
        for (int cc = 0; cc < 2; cc++) {
            const int kk = 2 * (1 - wh) + cc;
#pragma unroll
            for (int jp = 0; jp < 8; jp++) {
                int rr = 128 * wh + 16 * jp + ((lane >> 4) << 3) + (lane & 7);
                int byte = kk * 32 + ((lane >> 3) & 1) * 16;
                uint32_t Bv[4];
                ldsm4(sV + sw128(rr, byte), Bv);
                mma16816(accO[2*jp],   aQ[cc], Bv[0], Bv[1]);
                mma16816(accO[2*jp+1], aQ[cc], Bv[2], Bv[3]);
            }
        }
    }

    // ---- l reduction ----
    lsum0 += __shfl_xor_sync(0xffffffffu, lsum0, 1);
    lsum0 += __shfl_xor_sync(0xffffffffu, lsum0, 2);
    lsum1 += __shfl_xor_sync(0xffffffffu, lsum1, 1);
    lsum1 += __shfl_xor_sync(0xffffffffu, lsum1, 2);
    float* sL = (float*)(smem + SM_L);
    if (tig == 0) {
        sL[(r0 + g) * 2 + wh]     = lsum0;
        sL[(r0 + g + 8) * 2 + wh] = lsum1;
    }
    __syncthreads();
    const float rl0 = 1.0f / (sL[(r0 + g) * 2]     + sL[(r0 + g) * 2 + 1]);
    const float rl1 = 1.0f / (sL[(r0 + g + 8) * 2] + sL[(r0 + g + 8) * 2 + 1]);
    const float gam = gamma_p[0];

    // ---- epilogue: smem transpose, coalesced  out = gamma*O/l + g ----
    float* sT = (float*)(smem + SM_ST0);         // [64 ch][128 q] pad-132
#pragma unroll 1
    for (int blk = 0; blk < 4; blk++) {
        if (wh == (blk >> 1)) {
#pragma unroll
            for (int jj = 0; jj < 8; jj++) {
                int j  = 8 * (blk & 1) + jj;
                int cl = 8 * jj + 2 * tig;
                sT[(cl    ) * 132 + r0 + g]     = gam * accO[j][0] * rl0;
                sT[(cl + 1) * 132 + r0 + g]     = gam * accO[j][1] * rl0;
                sT[(cl    ) * 132 + r0 + g + 8] = gam * accO[j][2] * rl1;
                sT[(cl + 1) * 132 + r0 + g + 8] = gam * accO[j][3] * rl1;
            }
        }
        __syncthreads();
#pragma unroll
        for (int it = 0; it < 16; it++) {
            int idx = tid + it * 512;
            int q = idx & 127, cl = idx >> 7;
            size_t gi = (size_t)(b * CIN_ + 64 * blk + cl) * NPT + n0 + q;
            out[gi] = sT[cl * 132 + q] + gin[gi];
        }
        __syncthreads();
    }
}

// ================= launch =================
extern "C" void kernel_launch(void* const* d_in, const int* in_sizes, int n_in,
                              void* d_out, int out_size)
{
    const float* x     = (const float*)d_in[0];
    const float* g     = (const float*)d_in[1];
    const float* Wq    = (const float*)d_in[2];
    const float* bq    = (const float*)d_in[3];
    const float* Wk    = (const float*)d_in[4];
    const float* bk    = (const float*)d_in[5];
    const float* Wv    = (const float*)d_in[6];
    const float* bv    = (const float*)d_in[7];
    const float* gamma = (const float*)d_in[8];
    float* out = (float*)d_out;
    (void)in_sizes; (void)n_in; (void)out_size;

    cudaFuncSetAttribute(attn_tc, cudaFuncAttributeMaxDynamicSharedMemorySize, SMEM_TOTAL);

    proj_kernel<0><<<dim3(NPT / 64, CQK_ / 64, BSZ), 256>>>(Wq, bq, x);
    proj_kernel<1><<<dim3(NPT / 64, CQK_ / 64, BSZ), 256>>>(Wk, bk, g);
    proj_kernel<2><<<dim3(NPT / 64, CIN_ / 64, BSZ), 256>>>(Wv, bv, g);

    attn_tc<<<dim3(NPT / QT, BSZ), 512, SMEM_TOTAL>>>(g, gamma, out);
}

// round 11
// speedup vs baseline: 2.2072x; 1.1072x over previous
#include <cuda_runtime.h>
#include <cuda_bf16.h>
#include <cuda_fp16.h>
#include <cstdint>

#define BSZ 4
#define CIN_ 256
#define CQK_ 128
#define NPT 4096
#define KT 64            // keys per tile
#define NT 64            // tiles
#define QT 128           // queries per CTA

// scratch (device globals; no allocation allowed)
__device__ __half g_qh[BSZ * NPT * CQK_];          // [b][n][o] fp16 hi
__device__ __half g_ql[BSZ * NPT * CQK_];          // [b][n][o] fp16 lo
__device__ __half g_kh[BSZ * NPT * CQK_];          // [b][m][o] fp16 hi only
__device__ __nv_bfloat16 g_vh[BSZ * CIN_ * NPT];   // [b][c][m] bf16 channel-major

// ================= helpers =================
typedef unsigned long long u64;

__device__ __forceinline__ u64 pack2(float lo, float hi) {
    u64 r; asm("mov.b64 %0, {%1, %2};" : "=l"(r) : "f"(lo), "f"(hi)); return r;
}
__device__ __forceinline__ void unpack2(u64 v, float& lo, float& hi) {
    asm("mov.b64 {%0, %1}, %2;" : "=f"(lo), "=f"(hi) : "l"(v));
}
__device__ __forceinline__ void ffma2(u64& d, u64 a, u64 b) {
    asm("fma.rn.f32x2 %0, %1, %2, %0;" : "+l"(d) : "l"(a), "l"(b));
}
__device__ __forceinline__ uint32_t smem_u32(const void* p) {
    uint32_t a;
    asm("{ .reg .u64 t; cvta.to.shared.u64 t, %1; cvt.u32.u64 %0, t; }" : "=r"(a) : "l"(p));
    return a;
}
__device__ __forceinline__ void cp_async16(uint32_t dst, const void* src) {
    asm volatile("cp.async.cg.shared.global [%0], [%1], 16;" :: "r"(dst), "l"(src) : "memory");
}
#define CP_COMMIT() asm volatile("cp.async.commit_group;" ::: "memory")
#define CP_WAIT0()  asm volatile("cp.async.wait_group 0;" ::: "memory")

__device__ __forceinline__ void ldsm4(uint32_t addr, uint32_t r[4]) {
    asm volatile("ldmatrix.sync.aligned.m8n8.x4.shared.b16 {%0,%1,%2,%3}, [%4];"
        : "=r"(r[0]), "=r"(r[1]), "=r"(r[2]), "=r"(r[3]) : "r"(addr));
}
// fp16 MMA (S phase)
__device__ __forceinline__ void mma_f16(float c[4], const uint32_t a[4],
                                        uint32_t b0, uint32_t b1) {
    asm volatile("mma.sync.aligned.m16n8k16.row.col.f32.f16.f16.f32 "
        "{%0,%1,%2,%3}, {%4,%5,%6,%7}, {%8,%9}, {%0,%1,%2,%3};"
        : "+f"(c[0]), "+f"(c[1]), "+f"(c[2]), "+f"(c[3])
        : "r"(a[0]), "r"(a[1]), "r"(a[2]), "r"(a[3]), "r"(b0), "r"(b1));
}
// bf16 MMA (PV phase — P needs bf16 range)
__device__ __forceinline__ void mma_bf16(float c[4], const uint32_t a[4],
                                         uint32_t b0, uint32_t b1) {
    asm volatile("mma.sync.aligned.m16n8k16.row.col.f32.bf16.bf16.f32 "
        "{%0,%1,%2,%3}, {%4,%5,%6,%7}, {%8,%9}, {%0,%1,%2,%3};"
        : "+f"(c[0]), "+f"(c[1]), "+f"(c[2]), "+f"(c[3])
        : "r"(a[0]), "r"(a[1]), "r"(a[2]), "r"(a[3]), "r"(b0), "r"(b1));
}

// 256B-row swizzle (Q, K): conflict-free ldmatrix + cp.async
__device__ __forceinline__ uint32_t sw256(int r, int byte) {
    return (uint32_t)(r * 256 + (((byte >> 4) ^ (r & 7)) << 4) + (byte & 15));
}
// 128B-row swizzle (V): conflict-free
__device__ __forceinline__ uint32_t sw128(int r, int byte) {
    return (uint32_t)(r * 128 + (((byte >> 4) ^ (r & 7)) << 4) + (byte & 15));
}

__device__ __forceinline__ uint32_t h2u(float a, float b) {
    __half2 h = __floats2half2_rn(a, b);
    return *(uint32_t*)&h;
}
__device__ __forceinline__ uint32_t b2u(float a, float b) {
    __nv_bfloat162 h = __floats2bfloat162_rn(a, b);
    return *(uint32_t*)&h;
}

// ================= Projection GEMM (FFMA fp32, mixed outputs) =================
// out[b][n][o] = sum_c W[o][c] * X[b][c][n] + bias[o]
// DST 0: Q -> g_qh + g_ql (fp16 hi/lo). DST 1: K -> g_kh (fp16 hi).
// DST 2: V -> g_vh [b][c][m] bf16 (transposed store).
template<int DST>
__global__ __launch_bounds__(256)
void proj_kernel(const float* __restrict__ W, const float* __restrict__ bias,
                 const float* __restrict__ X)
{
    __shared__ float sX[32 * 64];
    __shared__ float sW[32 * 68];

    const int tid = threadIdx.x;
    const int tn = tid >> 4, to = tid & 15;
    const int b  = blockIdx.z;
    const int n0 = blockIdx.x * 64;
    const int o0 = blockIdx.y * 64;
    const float* Xb = X + (size_t)b * CIN_ * NPT;

    u64 acc[4][2];
#pragma unroll
    for (int i = 0; i < 4; i++) { acc[i][0] = 0ull; acc[i][1] = 0ull; }

    for (int ct = 0; ct < CIN_; ct += 32) {
#pragma unroll
        for (int r = 0; r < 8; r++) {
            int idx = tid + r * 256;
            int c = idx >> 6, n = idx & 63;
            sX[c * 64 + n] = Xb[(size_t)(ct + c) * NPT + n0 + n];
        }
#pragma unroll
        for (int r = 0; r < 8; r++) {
            int idx = tid + r * 256;
            int o = idx >> 5, c = idx & 31;
            sW[c * 68 + o] = W[(size_t)(o0 + o) * CIN_ + ct + c];
        }
        __syncthreads();
#pragma unroll 8
        for (int c = 0; c < 32; c++) {
            float4 xf = *(const float4*)&sX[c * 64 + 4 * tn];
            ulonglong2 wf = *(const ulonglong2*)&sW[c * 68 + 4 * to];
            u64 x0 = pack2(xf.x, xf.x), x1 = pack2(xf.y, xf.y);
            u64 x2 = pack2(xf.z, xf.z), x3 = pack2(xf.w, xf.w);
            ffma2(acc[0][0], x0, wf.x); ffma2(acc[0][1], x0, wf.y);
            ffma2(acc[1][0], x1, wf.x); ffma2(acc[1][1], x1, wf.y);
            ffma2(acc[2][0], x2, wf.x); ffma2(acc[2][1], x2, wf.y);
            ffma2(acc[3][0], x3, wf.x); ffma2(acc[3][1], x3, wf.y);
        }
        __syncthreads();
    }

    float4 bv4 = *(const float4*)&bias[o0 + 4 * to];
    float v[4][4];
#pragma unroll
    for (int i = 0; i < 4; i++) {
        unpack2(acc[i][0], v[i][0], v[i][1]); unpack2(acc[i][1], v[i][2], v[i][3]);
        v[i][0] += bv4.x; v[i][1] += bv4.y; v[i][2] += bv4.z; v[i][3] += bv4.w;
    }

    if (DST == 0) {            // Q: fp16 hi/lo split
#pragma unroll
        for (int i = 0; i < 4; i++) {
            float h0 = __half2float(__float2half_rn(v[i][0]));
            float h1 = __half2float(__float2half_rn(v[i][1]));
            float h2 = __half2float(__float2half_rn(v[i][2]));
            float h3 = __half2float(__float2half_rn(v[i][3]));
            size_t idx = (size_t)(b * NPT + n0 + 4 * tn + i) * CQK_ + o0 + 4 * to;
            *(uint2*)&g_qh[idx] = make_uint2(h2u(h0, h1), h2u(h2, h3));
            *(uint2*)&g_ql[idx] = make_uint2(h2u(v[i][0] - h0, v[i][1] - h1),
                                             h2u(v[i][2] - h2, v[i][3] - h3));
        }
    } else if (DST == 1) {     // K: fp16 hi only
#pragma unroll
        for (int i = 0; i < 4; i++) {
            size_t idx = (size_t)(b * NPT + n0 + 4 * tn + i) * CQK_ + o0 + 4 * to;
            *(uint2*)&g_kh[idx] = make_uint2(h2u(v[i][0], v[i][1]), h2u(v[i][2], v[i][3]));
        }
    } else {                   // V: [b][c][m], bf16
#pragma unroll
        for (int j = 0; j < 4; j++) {
            size_t idx = (size_t)(b * CIN_ + o0 + 4 * to + j) * NPT + n0 + 4 * tn;
            *(uint2*)&g_vh[idx] = make_uint2(b2u(v[0][j], v[1][j]), b2u(v[2][j], v[3][j]));
        }
    }
}

// ================= Fused mma.sync flash attention (fp16 S / bf16 PV) =================
// SMEM layout (bytes):
#define SM_QH   0u
#define SM_QL   32768u
#define SM_ST0  65536u       // stage: { Kh 16K | V 32K } = 48K, x2
#define STAGESZ 49152u
#define SM_P    163840u      // per-warp P fragment regions: 16 x 1KB
#define SM_MAX  180224u      // [128][2] f32
#define SM_L    181248u      // [128][2] f32
#define SMEM_TOTAL 182272

__device__ __forceinline__ void load_stage(uint32_t sb, int stage, int m0, int tid,
    const __half* kh, const __nv_bfloat16* vh)
{
    uint32_t stg = sb + SM_ST0 + (uint32_t)stage * STAGESZ;
#pragma unroll
    for (int i = 0; i < 6; i++) {
        int c = tid + i * 512;                       // 3072 chunks of 16B
        if (c < 1024) {                              // Kh: 64 rows x 256B
            int r = c >> 4, ch = c & 15;
            const __half* src = kh + (size_t)(m0 + r) * CQK_ + ch * 8;
            cp_async16(stg + sw256(r, ch * 16), src);
        } else {                                     // V: 256 ch x 128B
            int cc = c - 1024;
            int r = cc >> 3, ch = cc & 7;            // r = channel
            const __nv_bfloat16* src = vh + (size_t)r * NPT + m0 + ch * 8;
            cp_async16(stg + 16384u + sw128(r, ch * 16), src);
        }
    }
}

extern __shared__ __align__(16) char smem[];

__global__ __launch_bounds__(512, 1)
void attn_tc(const float* __restrict__ gin, const float* __restrict__ gamma_p,
             float* __restrict__ out)
{
    const uint32_t sb = smem_u32(smem);
    const int tid  = threadIdx.x;
    const int lane = tid & 31, wid = tid >> 5;
    const int wq = wid & 7, wh = wid >> 3;     // query group / half (keys in S, chans in PV)
    const int g = lane >> 2, tig = lane & 3;
    const int r0 = 16 * wq;
    const int b  = blockIdx.y;
    const int n0 = blockIdx.x * QT;

    const __half* qh = g_qh + (size_t)(b * NPT + n0) * CQK_;
    const __half* ql = g_ql + (size_t)(b * NPT + n0) * CQK_;
    const __half* kh = g_kh + (size_t)b * NPT * CQK_;
    const __nv_bfloat16* vh = g_vh + (size_t)b * CIN_ * NPT;

    // P fragment exchange regions (1KB per warp): [i 0..7][lane] u32
    const uint32_t pOwn  = sb + SM_P + (uint32_t)((wq * 2 + wh) * 1024) + (uint32_t)(lane * 4);
    const uint32_t pPeer = sb + SM_P + (uint32_t)((wq * 2 + (1 - wh)) * 1024) + (uint32_t)(lane * 4);

    // prologue: Q (hi+lo) + stage0
#pragma unroll
    for (int i = 0; i < 8; i++) {
        int c = tid + i * 512;
        int cc = c & 2047;
        int r = cc >> 4, ch = cc & 15;
        const __half* src = ((c < 2048) ? qh : ql) + (size_t)r * CQK_ + ch * 8;
        cp_async16(sb + ((c < 2048) ? SM_QH : SM_QL) + sw256(r, ch * 16), src);
    }
    load_stage(sb, 0, 0, tid, kh, vh);
    CP_COMMIT();

    float accO[16][4];
#pragma unroll
    for (int j = 0; j < 16; j++)
#pragma unroll
        for (int q = 0; q < 4; q++) accO[j][q] = 0.0f;

    float lsum0 = 0.0f, lsum1 = 0.0f;
    float m0r = 0.0f, m1r = 0.0f;
    const int n0w = 32 * wh;

    for (int t = 0; t < NT; t++) {
        CP_WAIT0();
        __syncthreads();            // the ONLY full-CTA barrier per tile
        if (t + 1 < NT) { load_stage(sb, (t + 1) & 1, (t + 1) * KT, tid, kh, vh); CP_COMMIT(); }

        const uint32_t stg = sb + SM_ST0 + (uint32_t)(t & 1) * STAGESZ;
        const uint32_t sKh = stg, sV = stg + 16384u;

        // ---- S = Qh·Kh + Ql·Kh  (16 rows x 32 keys per warp, fp16 2-pass) ----
        float accS[4][4];
#pragma unroll
        for (int j = 0; j < 4; j++)
#pragma unroll
            for (int q = 0; q < 4; q++) accS[j][q] = 0.0f;

#pragma unroll
        for (int kk = 0; kk < 8; kk++) {
            uint32_t Ah[4], Al[4];
            {
                int rr = r0 + (lane & 15);
                int byte = kk * 32 + ((lane >> 4) & 1) * 16;
                ldsm4(sb + SM_QH + sw256(rr, byte), Ah);
                ldsm4(sb + SM_QL + sw256(rr, byte), Al);
            }
#pragma unroll
            for (int jp = 0; jp < 2; jp++) {
                int rr = n0w + 16 * jp + ((lane >> 4) << 3) + (lane & 7);
                int byte = kk * 32 + ((lane >> 3) & 1) * 16;
                uint32_t Bh[4];
                ldsm4(sKh + sw256(rr, byte), Bh);
                mma_f16(accS[2*jp],   Ah, Bh[0], Bh[1]);
                mma_f16(accS[2*jp+1], Ah, Bh[2], Bh[3]);
                mma_f16(accS[2*jp],   Al, Bh[0], Bh[1]);
                mma_f16(accS[2*jp+1], Al, Bh[2], Bh[3]);
            }
        }

        // ---- fixed row max from tile 0 ----
        if (t == 0) {
            float mA = fmaxf(fmaxf(accS[0][0], accS[0][1]), fmaxf(accS[1][0], accS[1][1]));
            mA = fmaxf(mA, fmaxf(fmaxf(accS[2][0], accS[2][1]), fmaxf(accS[3][0], accS[3][1])));
            float mB = fmaxf(fmaxf(accS[0][2], accS[0][3]), fmaxf(accS[1][2], accS[1][3]));
            mB = fmaxf(mB, fmaxf(fmaxf(accS[2][2], accS[2][3]), fmaxf(accS[3][2], accS[3][3])));
            mA = fmaxf(mA, __shfl_xor_sync(0xffffffffu, mA, 1));
            mA = fmaxf(mA, __shfl_xor_sync(0xffffffffu, mA, 2));
            mB = fmaxf(mB, __shfl_xor_sync(0xffffffffu, mB, 1));
            mB = fmaxf(mB, __shfl_xor_sync(0xffffffffu, mB, 2));
            float* sM = (float*)(smem + SM_MAX);
            if (tig == 0) {
                sM[(r0 + g) * 2 + wh]     = mA;
                sM[(r0 + g + 8) * 2 + wh] = mB;
            }
            __syncthreads();
            m0r = fmaxf(sM[(r0 + g) * 2],     sM[(r0 + g) * 2 + 1]);
            m1r = fmaxf(sM[(r0 + g + 8) * 2], sM[(r0 + g + 8) * 2 + 1]);
        }

        // ---- softmax: accS -> bf16 A-fragments in registers; l from rounded P ----
        uint32_t aP[2][4];
#pragma unroll
        for (int j = 0; j < 4; j++) {
            float e0 = __expf(accS[j][0] - m0r);
            float e1 = __expf(accS[j][1] - m0r);
            float e2 = __expf(accS[j][2] - m1r);
            float e3 = __expf(accS[j][3] - m1r);
            __nv_bfloat162 p01 = __floats2bfloat162_rn(e0, e1);
            __nv_bfloat162 p23 = __floats2bfloat162_rn(e2, e3);
            lsum0 += __bfloat162float(p01.x) + __bfloat162float(p01.y);
            lsum1 += __bfloat162float(p23.x) + __bfloat162float(p23.y);
            aP[j >> 1][((j & 1) << 1)]     = *(uint32_t*)&p01;   // a0/a2: row g
            aP[j >> 1][((j & 1) << 1) | 1] = *(uint32_t*)&p23;   // a1/a3: row g+8
        }

        // store own fragments for partner (SoA: conflict-free)
#pragma unroll
        for (int i = 0; i < 8; i++)
            *(uint32_t*)(smem + (pOwn - sb) + (uint32_t)(i * 128)) = aP[i >> 2][i & 3];

        // ---- PV own key-chunks first (hide partner skew under mma) ----
#pragma unroll
        for (int cc = 0; cc < 2; cc++) {
            const int kk = 2 * wh + cc;                 // global k16 chunk
#pragma unroll
            for (int jp = 0; jp < 8; jp++) {
                int rr = 128 * wh + 16 * jp + ((lane >> 4) << 3) + (lane & 7);
                int byte = kk * 32 + ((lane >> 3) & 1) * 16;
                uint32_t Bv[4];
                ldsm4(sV + sw128(rr, byte), Bv);
                mma_bf16(accO[2*jp],   aP[cc], Bv[0], Bv[1]);
                mma_bf16(accO[2*jp+1], aP[cc], Bv[2], Bv[3]);
            }
        }

        // pair barrier: partner's fragments visible
        asm volatile("bar.sync %0, %1;" :: "r"(1 + wq), "r"(64) : "memory");

        uint32_t aQ[2][4];
#pragma unroll
        for (int i = 0; i < 8; i++)
            aQ[i >> 2][i & 3] = *(const uint32_t*)(smem + (pPeer - sb) + (uint32_t)(i * 128));

        // ---- PV partner key-chunks ----
#pragma unroll
        for (int cc = 0; cc < 2; cc++) {
            const int kk = 2 * (1 - wh) + cc;
#pragma unroll
            for (int jp = 0; jp < 8; jp++) {
                int rr = 128 * wh + 16 * jp + ((lane >> 4) << 3) + (lane & 7);
                int byte = kk * 32 + ((lane >> 3) & 1) * 16;
                uint32_t Bv[4];
                ldsm4(sV + sw128(rr, byte), Bv);
                mma_bf16(accO[2*jp],   aQ[cc], Bv[0], Bv[1]);
                mma_bf16(accO[2*jp+1], aQ[cc], Bv[2], Bv[3]);
            }
        }
    }

    // ---- l reduction ----
    lsum0 += __shfl_xor_sync(0xffffffffu, lsum0, 1);
    lsum0 += __shfl_xor_sync(0xffffffffu, lsum0, 2);
    lsum1 += __shfl_xor_sync(0xffffffffu, lsum1, 1);
    lsum1 += __shfl_xor_sync(0xffffffffu, lsum1, 2);
    float* sL = (float*)(smem + SM_L);
    if (tig == 0) {
        sL[(r0 + g) * 2 + wh]     = lsum0;
        sL[(r0 + g + 8) * 2 + wh] = lsum1;
    }
    __syncthreads();
    const float rl0 = 1.0f / (sL[(r0 + g) * 2]     + sL[(r0 + g) * 2 + 1]);
    const float rl1 = 1.0f / (sL[(r0 + g + 8) * 2] + sL[(r0 + g + 8) * 2 + 1]);
    const float gam = gamma_p[0];

    // ---- epilogue: smem transpose, coalesced  out = gamma*O/l + g ----
    float* sT = (float*)(smem + SM_ST0);         // [64 ch][128 q] pad-132
#pragma unroll 1
    for (int blk = 0; blk < 4; blk++) {
        if (wh == (blk >> 1)) {
#pragma unroll
            for (int jj = 0; jj < 8; jj++) {
                int j  = 8 * (blk & 1) + jj;
                int cl = 8 * jj + 2 * tig;
                sT[(cl    ) * 132 + r0 + g]     = gam * accO[j][0] * rl0;
                sT[(cl + 1) * 132 + r0 + g]     = gam * accO[j][1] * rl0;
                sT[(cl    ) * 132 + r0 + g + 8] = gam * accO[j][2] * rl1;
                sT[(cl + 1) * 132 + r0 + g + 8] = gam * accO[j][3] * rl1;
            }
        }
        __syncthreads();
#pragma unroll
        for (int it = 0; it < 16; it++) {
            int idx = tid + it * 512;
            int q = idx & 127, cl = idx >> 7;
            size_t gi = (size_t)(b * CIN_ + 64 * blk + cl) * NPT + n0 + q;
            out[gi] = sT[cl * 132 + q] + gin[gi];
        }
        __syncthreads();
    }
}

// ================= launch =================
extern "C" void kernel_launch(void* const* d_in, const int* in_sizes, int n_in,
                              void* d_out, int out_size)
{
    const float* x     = (const float*)d_in[0];
    const float* g     = (const float*)d_in[1];
    const float* Wq    = (const float*)d_in[2];
    const float* bq    = (const float*)d_in[3];
    const float* Wk    = (const float*)d_in[4];
    const float* bk    = (const float*)d_in[5];
    const float* Wv    = (const float*)d_in[6];
    const float* bv    = (const float*)d_in[7];
    const float* gamma = (const float*)d_in[8];
    float* out = (float*)d_out;
    (void)in_sizes; (void)n_in; (void)out_size;

    cudaFuncSetAttribute(attn_tc, cudaFuncAttributeMaxDynamicSharedMemorySize, SMEM_TOTAL);

    proj_kernel<0><<<dim3(NPT / 64, CQK_ / 64, BSZ), 256>>>(Wq, bq, x);
    proj_kernel<1><<<dim3(NPT / 64, CQK_ / 64, BSZ), 256>>>(Wk, bk, g);
    proj_kernel<2><<<dim3(NPT / 64, CIN_ / 64, BSZ), 256>>>(Wv, bv, g);

    attn_tc<<<dim3(NPT / QT, BSZ), 512, SMEM_TOTAL>>>(g, gamma, out);
}

// round 12
// speedup vs baseline: 2.6896x; 1.2185x over previous
#include <cuda_runtime.h>
#include <cuda_bf16.h>
#include <cuda_fp16.h>
#include <cstdint>

#define BSZ 4
#define CIN_ 256
#define CQK_ 128
#define NPT 4096
#define KT 64            // keys per tile (attention)
#define NT 64            // tiles
#define QT 128           // queries per CTA

// scratch (device globals; no allocation allowed)
__device__ __half g_qh[BSZ * NPT * CQK_];          // [b][n][o] fp16 hi
__device__ __half g_ql[BSZ * NPT * CQK_];          // [b][n][o] fp16 lo
__device__ __half g_kh[BSZ * NPT * CQK_];          // [b][m][o] fp16 hi only
__device__ __nv_bfloat16 g_vh[BSZ * CIN_ * NPT];   // [b][c][m] bf16 channel-major
// projection inputs, bf16 hi/lo, transposed to [b][n][c]
__device__ __nv_bfloat16 g_xh[BSZ * NPT * CIN_];
__device__ __nv_bfloat16 g_xl[BSZ * NPT * CIN_];
__device__ __nv_bfloat16 g_gh[BSZ * NPT * CIN_];
__device__ __nv_bfloat16 g_gl[BSZ * NPT * CIN_];
// weights bf16 hi/lo, [o 0..511][c] (Q rows 0-127, K 128-255, V 256-511)
__device__ __nv_bfloat16 g_wh[512 * CIN_];
__device__ __nv_bfloat16 g_wl[512 * CIN_];

// ================= helpers =================
__device__ __forceinline__ uint32_t smem_u32(const void* p) {
    uint32_t a;
    asm("{ .reg .u64 t; cvta.to.shared.u64 t, %1; cvt.u32.u64 %0, t; }" : "=r"(a) : "l"(p));
    return a;
}
__device__ __forceinline__ void cp_async16(uint32_t dst, const void* src) {
    asm volatile("cp.async.cg.shared.global [%0], [%1], 16;" :: "r"(dst), "l"(src) : "memory");
}
#define CP_COMMIT() asm volatile("cp.async.commit_group;" ::: "memory")
#define CP_WAIT0()  asm volatile("cp.async.wait_group 0;" ::: "memory")

__device__ __forceinline__ void ldsm4(uint32_t addr, uint32_t r[4]) {
    asm volatile("ldmatrix.sync.aligned.m8n8.x4.shared.b16 {%0,%1,%2,%3}, [%4];"
        : "=r"(r[0]), "=r"(r[1]), "=r"(r[2]), "=r"(r[3]) : "r"(addr));
}
// NOTE: mma wrappers intentionally NON-volatile (register-only ops) so ptxas
// can software-pipeline across the volatile ldsm anchors.
__device__ __forceinline__ void mma_f16(float c[4], const uint32_t a[4],
                                        uint32_t b0, uint32_t b1) {
    asm("mma.sync.aligned.m16n8k16.row.col.f32.f16.f16.f32 "
        "{%0,%1,%2,%3}, {%4,%5,%6,%7}, {%8,%9}, {%0,%1,%2,%3};"
        : "+f"(c[0]), "+f"(c[1]), "+f"(c[2]), "+f"(c[3])
        : "r"(a[0]), "r"(a[1]), "r"(a[2]), "r"(a[3]), "r"(b0), "r"(b1));
}
__device__ __forceinline__ void mma_bf16(float c[4], const uint32_t a[4],
                                         uint32_t b0, uint32_t b1) {
    asm("mma.sync.aligned.m16n8k16.row.col.f32.bf16.bf16.f32 "
        "{%0,%1,%2,%3}, {%4,%5,%6,%7}, {%8,%9}, {%0,%1,%2,%3};"
        : "+f"(c[0]), "+f"(c[1]), "+f"(c[2]), "+f"(c[3])
        : "r"(a[0]), "r"(a[1]), "r"(a[2]), "r"(a[3]), "r"(b0), "r"(b1));
}

// 256B-row swizzle (Q, K in attention)
__device__ __forceinline__ uint32_t sw256(int r, int byte) {
    return (uint32_t)(r * 256 + (((byte >> 4) ^ (r & 7)) << 4) + (byte & 15));
}
// 128B-row swizzle (V, proj tiles)
__device__ __forceinline__ uint32_t sw128(int r, int byte) {
    return (uint32_t)(r * 128 + (((byte >> 4) ^ (r & 7)) << 4) + (byte & 15));
}

__device__ __forceinline__ uint32_t h2u(float a, float b) {
    __half2 h = __floats2half2_rn(a, b);
    return *(uint32_t*)&h;
}
__device__ __forceinline__ uint32_t b2u(float a, float b) {
    __nv_bfloat162 h = __floats2bfloat162_rn(a, b);
    return *(uint32_t*)&h;
}

extern __shared__ __align__(16) char smem[];

// ================= conversion kernels =================
// W -> bf16 hi/lo [o 0..511][c]
__global__ __launch_bounds__(256)
void conv_w(const float* __restrict__ Wq, const float* __restrict__ Wk,
            const float* __restrict__ Wv)
{
    int idx = blockIdx.x * 256 + threadIdx.x;      // [0, 512*256)
    int o = idx >> 8, c = idx & 255;
    float v = (o < 128) ? Wq[o * 256 + c]
            : (o < 256) ? Wk[(o - 128) * 256 + c]
                        : Wv[(o - 256) * 256 + c];
    __nv_bfloat16 h = __float2bfloat16_rn(v);
    g_wh[idx] = h;
    g_wl[idx] = __float2bfloat16_rn(v - __bfloat162float(h));
}

// x / g fp32 [b][c][n] -> bf16 hi/lo transposed [b][n][c]
__global__ __launch_bounds__(256)
void conv_xg(const float* __restrict__ x, const float* __restrict__ gg)
{
    __shared__ float s[32][33];
    const int tid = threadIdx.x;
    const int b = blockIdx.z & 3;
    const bool isx = blockIdx.z < 4;
    const float* src = (isx ? x : gg) + (size_t)b * CIN_ * NPT;
    __nv_bfloat16* dh = (isx ? g_xh : g_gh) + (size_t)b * NPT * CIN_;
    __nv_bfloat16* dl = (isx ? g_xl : g_gl) + (size_t)b * NPT * CIN_;
    const int n0 = blockIdx.x * 32, c0 = blockIdx.y * 32;
#pragma unroll
    for (int i = 0; i < 4; i++) {
        int idx = tid + i * 256;
        int c = idx >> 5, n = idx & 31;
        s[c][n] = src[(size_t)(c0 + c) * NPT + n0 + n];
    }
    __syncthreads();
#pragma unroll
    for (int i = 0; i < 2; i++) {
        int idx = tid + i * 256;
        int n = idx >> 4, cp = idx & 15;
        float v0 = s[2 * cp][n], v1 = s[2 * cp + 1][n];
        __nv_bfloat16 h0 = __float2bfloat16_rn(v0), h1 = __float2bfloat16_rn(v1);
        size_t o = (size_t)(n0 + n) * CIN_ + c0 + 2 * cp;
        *(uint32_t*)&dh[o] = (uint32_t)__bfloat16_as_ushort(h0) |
                             ((uint32_t)__bfloat16_as_ushort(h1) << 16);
        *(uint32_t*)&dl[o] = b2u(v0 - __bfloat162float(h0), v1 - __bfloat162float(h1));
    }
}

// ================= tensor-core projection GEMM =================
// C[n, o] = sum_c X[n,c]*W[o,c] + bias[o], 3-pass bf16 split (fp32-accurate).
// CTA: 128 n x 64 o, K = 256 in 4 chunks of 64. 8 warps, warp = 16n x 64o.
#define PSTAGE 49152u        // { Ah 16K | Al 16K | Bh 8K | Bl 8K }
#define PBIAS  98304u
#define PROJ_SMEM 98560

__device__ __forceinline__ void load_pstage(uint32_t sb, int stage, int ct, int tid,
    const __nv_bfloat16* ah, const __nv_bfloat16* al, int b, int n0, int o0)
{
    uint32_t stg = sb + (uint32_t)stage * PSTAGE;
#pragma unroll
    for (int i = 0; i < 12; i++) {
        int c = tid + i * 256;                       // 3072 chunks of 16B
        if (c < 2048) {                              // A hi/lo: 128 rows x 128B
            const __nv_bfloat16* s = (c < 1024) ? ah : al;
            int cc = c & 1023;
            int r = cc >> 3, ch = cc & 7;
            const __nv_bfloat16* src = s + (size_t)(b * NPT + n0 + r) * CIN_ + ct * 64 + ch * 8;
            cp_async16(stg + ((c < 1024) ? 0u : 16384u) + sw128(r, ch * 16), src);
        } else {                                     // B hi/lo: 64 rows x 128B
            const __nv_bfloat16* s = (c < 2560) ? g_wh : g_wl;
            int cc = c & 511;
            int r = cc >> 3, ch = cc & 7;
            const __nv_bfloat16* src = s + (size_t)(o0 + r) * CIN_ + ct * 64 + ch * 8;
            cp_async16(stg + ((c < 2560) ? 32768u : 40960u) + sw128(r, ch * 16), src);
        }
    }
}

__global__ __launch_bounds__(256)
void proj_mma(const float* __restrict__ bq, const float* __restrict__ bk,
              const float* __restrict__ bv)
{
    const uint32_t sb = smem_u32(smem);
    const int tid = threadIdx.x;
    const int lane = tid & 31, wid = tid >> 5;
    const int g = lane >> 2, tig = lane & 3;
    const int r0 = wid * 16;
    const int b  = blockIdx.z;
    const int n0 = blockIdx.x * 128;
    const int oy = blockIdx.y;
    const int o0 = oy * 64;
    const int dstT = (oy < 2) ? 0 : (oy < 4) ? 1 : 2;   // Q / K / V

    const __nv_bfloat16* ah = (dstT == 0) ? g_xh : g_gh;
    const __nv_bfloat16* al = (dstT == 0) ? g_xl : g_gl;
    const float* biasp = (dstT == 0) ? (bq + o0) : (dstT == 1) ? (bk + o0 - 128) : (bv + o0 - 256);

    float* sBias = (float*)(smem + PBIAS);
    if (tid < 64) sBias[tid] = biasp[tid];

    load_pstage(sb, 0, 0, tid, ah, al, b, n0, o0);
    CP_COMMIT();

    float accC[8][4];
#pragma unroll
    for (int j = 0; j < 8; j++)
#pragma unroll
        for (int q = 0; q < 4; q++) accC[j][q] = 0.0f;

    for (int ct = 0; ct < 4; ct++) {
        CP_WAIT0();
        __syncthreads();
        if (ct < 3) { load_pstage(sb, (ct + 1) & 1, ct + 1, tid, ah, al, b, n0, o0); CP_COMMIT(); }

        const uint32_t stg = sb + (uint32_t)(ct & 1) * PSTAGE;
#pragma unroll
        for (int kk = 0; kk < 4; kk++) {
            uint32_t Ah[4], Al[4];
            {
                int rr = r0 + (lane & 15);
                int byte = kk * 32 + ((lane >> 4) & 1) * 16;
                ldsm4(stg + sw128(rr, byte), Ah);
                ldsm4(stg + 16384u + sw128(rr, byte), Al);
            }
#pragma unroll
            for (int jb = 0; jb < 4; jb++) {
                int rr = jb * 16 + ((lane >> 4) << 3) + (lane & 7);
                int byte = kk * 32 + ((lane >> 3) & 1) * 16;
                uint32_t Bh[4], Bl[4];
                ldsm4(stg + 32768u + sw128(rr, byte), Bh);
                ldsm4(stg + 40960u + sw128(rr, byte), Bl);
                mma_bf16(accC[2*jb],   Ah, Bh[0], Bh[1]);
                mma_bf16(accC[2*jb+1], Ah, Bh[2], Bh[3]);
                mma_bf16(accC[2*jb],   Al, Bh[0], Bh[1]);
                mma_bf16(accC[2*jb+1], Al, Bh[2], Bh[3]);
                mma_bf16(accC[2*jb],   Ah, Bl[0], Bl[1]);
                mma_bf16(accC[2*jb+1], Ah, Bl[2], Bl[3]);
            }
        }
    }
    __syncthreads();     // all smem reads done; sBias loaded; stage area reusable

    if (dstT < 2) {      // Q / K: [b][n][o] fp16 (Q also lo part)
#pragma unroll
        for (int jb = 0; jb < 4; jb++)
#pragma unroll
            for (int hb = 0; hb < 2; hb++) {
                int ol = jb * 16 + hb * 8 + 2 * tig;
                float b0 = sBias[ol], b1 = sBias[ol + 1];
                float* a = accC[2 * jb + hb];
                float v00 = a[0] + b0, v01 = a[1] + b1;   // row r0+g
                float v10 = a[2] + b0, v11 = a[3] + b1;   // row r0+g+8
                int og = (dstT == 0) ? o0 : (o0 - 128);
                size_t i0 = (size_t)(b * NPT + n0 + r0 + g) * CQK_ + og + ol;
                size_t i1 = i0 + (size_t)8 * CQK_;
                if (dstT == 0) {
                    float h00 = __half2float(__float2half_rn(v00));
                    float h01 = __half2float(__float2half_rn(v01));
                    float h10 = __half2float(__float2half_rn(v10));
                    float h11 = __half2float(__float2half_rn(v11));
                    *(uint32_t*)&g_qh[i0] = h2u(h00, h01);
                    *(uint32_t*)&g_qh[i1] = h2u(h10, h11);
                    *(uint32_t*)&g_ql[i0] = h2u(v00 - h00, v01 - h01);
                    *(uint32_t*)&g_ql[i1] = h2u(v10 - h10, v11 - h11);
                } else {
                    *(uint32_t*)&g_kh[i0] = h2u(v00, v01);
                    *(uint32_t*)&g_kh[i1] = h2u(v10, v11);
                }
            }
    } else {             // V: transpose to [b][c][m] bf16 via smem
        __nv_bfloat16* sT = (__nv_bfloat16*)smem;    // [64][130]
#pragma unroll
        for (int jb = 0; jb < 4; jb++)
#pragma unroll
            for (int hb = 0; hb < 2; hb++) {
                int ol = jb * 16 + hb * 8 + 2 * tig;
                float b0 = sBias[ol], b1 = sBias[ol + 1];
                float* a = accC[2 * jb + hb];
                sT[(ol    ) * 130 + r0 + g]     = __float2bfloat16_rn(a[0] + b0);
                sT[(ol + 1) * 130 + r0 + g]     = __float2bfloat16_rn(a[1] + b1);
                sT[(ol    ) * 130 + r0 + g + 8] = __float2bfloat16_rn(a[2] + b0);
                sT[(ol + 1) * 130 + r0 + g + 8] = __float2bfloat16_rn(a[3] + b1);
            }
        __syncthreads();
#pragma unroll
        for (int i = 0; i < 16; i++) {
            int w = tid + i * 256;                   // 4096 u32 words
            int o = w >> 6, nn = (w & 63) * 2;
            uint32_t val = *(uint32_t*)&sT[o * 130 + nn];
            *(uint32_t*)&g_vh[(size_t)(b * CIN_ + (o0 - 256) + o) * NPT + n0 + nn] = val;
        }
    }
}

// ================= Fused mma.sync flash attention (fp16 S / bf16 PV) =================
#define SM_QH   0u
#define SM_QL   32768u
#define SM_ST0  65536u       // stage: { Kh 16K | V 32K } = 48K, x2
#define STAGESZ 49152u
#define SM_P    163840u      // per-warp P fragment regions: 16 x 1KB
#define SM_MAX  180224u      // [128][2] f32
#define SM_L    181248u      // [128][2] f32
#define SMEM_TOTAL 182272

__device__ __forceinline__ void load_stage(uint32_t sb, int stage, int m0, int tid,
    const __half* kh, const __nv_bfloat16* vh)
{
    uint32_t stg = sb + SM_ST0 + (uint32_t)stage * STAGESZ;
#pragma unroll
    for (int i = 0; i < 6; i++) {
        int c = tid + i * 512;                       // 3072 chunks of 16B
        if (c < 1024) {                              // Kh: 64 rows x 256B
            int r = c >> 4, ch = c & 15;
            const __half* src = kh + (size_t)(m0 + r) * CQK_ + ch * 8;
            cp_async16(stg + sw256(r, ch * 16), src);
        } else {                                     // V: 256 ch x 128B
            int cc = c - 1024;
            int r = cc >> 3, ch = cc & 7;            // r = channel
            const __nv_bfloat16* src = vh + (size_t)r * NPT + m0 + ch * 8;
            cp_async16(stg + 16384u + sw128(r, ch * 16), src);
        }
    }
}

__global__ __launch_bounds__(512, 1)
void attn_tc(const float* __restrict__ gin, const float* __restrict__ gamma_p,
             float* __restrict__ out)
{
    const uint32_t sb = smem_u32(smem);
    const int tid  = threadIdx.x;
    const int lane = tid & 31, wid = tid >> 5;
    const int wq = wid & 7, wh = wid >> 3;
    const int g = lane >> 2, tig = lane & 3;
    const int r0 = 16 * wq;
    const int b  = blockIdx.y;
    const int n0 = blockIdx.x * QT;

    const __half* qh = g_qh + (size_t)(b * NPT + n0) * CQK_;
    const __half* ql = g_ql + (size_t)(b * NPT + n0) * CQK_;
    const __half* kh = g_kh + (size_t)b * NPT * CQK_;
    const __nv_bfloat16* vh = g_vh + (size_t)b * CIN_ * NPT;

    const uint32_t pOwn  = sb + SM_P + (uint32_t)((wq * 2 + wh) * 1024) + (uint32_t)(lane * 4);
    const uint32_t pPeer = sb + SM_P + (uint32_t)((wq * 2 + (1 - wh)) * 1024) + (uint32_t)(lane * 4);

#pragma unroll
    for (int i = 0; i < 8; i++) {
        int c = tid + i * 512;
        int cc = c & 2047;
        int r = cc >> 4, ch = cc & 15;
        const __half* src = ((c < 2048) ? qh : ql) + (size_t)r * CQK_ + ch * 8;
        cp_async16(sb + ((c < 2048) ? SM_QH : SM_QL) + sw256(r, ch * 16), src);
    }
    load_stage(sb, 0, 0, tid, kh, vh);
    CP_COMMIT();

    float accO[16][4];
#pragma unroll
    for (int j = 0; j < 16; j++)
#pragma unroll
        for (int q = 0; q < 4; q++) accO[j][q] = 0.0f;

    float lsum0 = 0.0f, lsum1 = 0.0f;
    float m0r = 0.0f, m1r = 0.0f;
    const int n0w = 32 * wh;

    for (int t = 0; t < NT; t++) {
        CP_WAIT0();
        __syncthreads();
        if (t + 1 < NT) { load_stage(sb, (t + 1) & 1, (t + 1) * KT, tid, kh, vh); CP_COMMIT(); }

        const uint32_t stg = sb + SM_ST0 + (uint32_t)(t & 1) * STAGESZ;
        const uint32_t sKh = stg, sV = stg + 16384u;

        float accS[4][4];
#pragma unroll
        for (int j = 0; j < 4; j++)
#pragma unroll
            for (int q = 0; q < 4; q++) accS[j][q] = 0.0f;

#pragma unroll
        for (int kk = 0; kk < 8; kk++) {
            uint32_t Ah[4], Al[4];
            {
                int rr = r0 + (lane & 15);
                int byte = kk * 32 + ((lane >> 4) & 1) * 16;
                ldsm4(sb + SM_QH + sw256(rr, byte), Ah);
                ldsm4(sb + SM_QL + sw256(rr, byte), Al);
            }
#pragma unroll
            for (int jp = 0; jp < 2; jp++) {
                int rr = n0w + 16 * jp + ((lane >> 4) << 3) + (lane & 7);
                int byte = kk * 32 + ((lane >> 3) & 1) * 16;
                uint32_t Bh[4];
                ldsm4(sKh + sw256(rr, byte), Bh);
                mma_f16(accS[2*jp],   Ah, Bh[0], Bh[1]);
                mma_f16(accS[2*jp+1], Ah, Bh[2], Bh[3]);
                mma_f16(accS[2*jp],   Al, Bh[0], Bh[1]);
                mma_f16(accS[2*jp+1], Al, Bh[2], Bh[3]);
            }
        }

        if (t == 0) {
            float mA = fmaxf(fmaxf(accS[0][0], accS[0][1]), fmaxf(accS[1][0], accS[1][1]));
            mA = fmaxf(mA, fmaxf(fmaxf(accS[2][0], accS[2][1]), fmaxf(accS[3][0], accS[3][1])));
            float mB = fmaxf(fmaxf(accS[0][2], accS[0][3]), fmaxf(accS[1][2], accS[1][3]));
            mB = fmaxf(mB, fmaxf(fmaxf(accS[2][2], accS[2][3]), fmaxf(accS[3][2], accS[3][3])));
            mA = fmaxf(mA, __shfl_xor_sync(0xffffffffu, mA, 1));
            mA = fmaxf(mA, __shfl_xor_sync(0xffffffffu, mA, 2));
            mB = fmaxf(mB, __shfl_xor_sync(0xffffffffu, mB, 1));
            mB = fmaxf(mB, __shfl_xor_sync(0xffffffffu, mB, 2));
            float* sM = (float*)(smem + SM_MAX);
            if (tig == 0) {
                sM[(r0 + g) * 2 + wh]     = mA;
                sM[(r0 + g + 8) * 2 + wh] = mB;
            }
            __syncthreads();
            m0r = fmaxf(sM[(r0 + g) * 2],     sM[(r0 + g) * 2 + 1]);
            m1r = fmaxf(sM[(r0 + g + 8) * 2], sM[(r0 + g + 8) * 2 + 1]);
        }

        uint32_t aP[2][4];
#pragma unroll
        for (int j = 0; j < 4; j++) {
            float e0 = __expf(accS[j][0] - m0r);
            float e1 = __expf(accS[j][1] - m0r);
            float e2 = __expf(accS[j][2] - m1r);
            float e3 = __expf(accS[j][3] - m1r);
            __nv_bfloat162 p01 = __floats2bfloat162_rn(e0, e1);
            __nv_bfloat162 p23 = __floats2bfloat162_rn(e2, e3);
            lsum0 += __bfloat162float(p01.x) + __bfloat162float(p01.y);
            lsum1 += __bfloat162float(p23.x) + __bfloat162float(p23.y);
            aP[j >> 1][((j & 1) << 1)]     = *(uint32_t*)&p01;
            aP[j >> 1][((j & 1) << 1) | 1] = *(uint32_t*)&p23;
        }

#pragma unroll
        for (int i = 0; i < 8; i++)
            *(uint32_t*)(smem + (pOwn - sb) + (uint32_t)(i * 128)) = aP[i >> 2][i & 3];

#pragma unroll
        for (int cc = 0; cc < 2; cc++) {
            const int kk = 2 * wh + cc;
#pragma unroll
            for (int jp = 0; jp < 8; jp++) {
                int rr = 128 * wh + 16 * jp + ((lane >> 4) << 3) + (lane & 7);
                int byte = kk * 32 + ((lane >> 3) & 1) * 16;
                uint32_t Bv[4];
                ldsm4(sV + sw128(rr, byte), Bv);
                mma_bf16(accO[2*jp],   aP[cc], Bv[0], Bv[1]);
                mma_bf16(accO[2*jp+1], aP[cc], Bv[2], Bv[3]);
            }
        }

        asm volatile("bar.sync %0, %1;" :: "r"(1 + wq), "r"(64) : "memory");

        uint32_t aQ[2][4];
#pragma unroll
        for (int i = 0; i < 8; i++)
            aQ[i >> 2][i & 3] = *(const uint32_t*)(smem + (pPeer - sb) + (uint32_t)(i * 128));

#pragma unroll
        for (int cc = 0; cc < 2; cc++) {
            const int kk = 2 * (1 - wh) + cc;
#pragma unroll
            for (int jp = 0; jp < 8; jp++) {
                int rr = 128 * wh + 16 * jp + ((lane >> 4) << 3) + (lane & 7);
                int byte = kk * 32 + ((lane >> 3) & 1) * 16;
                uint32_t Bv[4];
                ldsm4(sV + sw128(rr, byte), Bv);
                mma_bf16(accO[2*jp],   aQ[cc], Bv[0], Bv[1]);
                mma_bf16(accO[2*jp+1], aQ[cc], Bv[2], Bv[3]);
            }
        }
    }

    lsum0 += __shfl_xor_sync(0xffffffffu, lsum0, 1);
    lsum0 += __shfl_xor_sync(0xffffffffu, lsum0, 2);
    lsum1 += __shfl_xor_sync(0xffffffffu, lsum1, 1);
    lsum1 += __shfl_xor_sync(0xffffffffu, lsum1, 2);
    float* sL = (float*)(smem + SM_L);
    if (tig == 0) {
        sL[(r0 + g) * 2 + wh]     = lsum0;
        sL[(r0 + g + 8) * 2 + wh] = lsum1;
    }
    __syncthreads();
    const float rl0 = 1.0f / (sL[(r0 + g) * 2]     + sL[(r0 + g) * 2 + 1]);
    const float rl1 = 1.0f / (sL[(r0 + g + 8) * 2] + sL[(r0 + g + 8) * 2 + 1]);
    const float gam = gamma_p[0];

    float* sT = (float*)(smem + SM_ST0);         // [64 ch][128 q] pad-132
#pragma unroll 1
    for (int blk = 0; blk < 4; blk++) {
        if (wh == (blk >> 1)) {
#pragma unroll
            for (int jj = 0; jj < 8; jj++) {
                int j  = 8 * (blk & 1) + jj;
                int cl = 8 * jj + 2 * tig;
                sT[(cl    ) * 132 + r0 + g]     = gam * accO[j][0] * rl0;
                sT[(cl + 1) * 132 + r0 + g]     = gam * accO[j][1] * rl0;
                sT[(cl    ) * 132 + r0 + g + 8] = gam * accO[j][2] * rl1;
                sT[(cl + 1) * 132 + r0 + g + 8] = gam * accO[j][3] * rl1;
            }
        }
        __syncthreads();
#pragma unroll
        for (int it = 0; it < 16; it++) {
            int idx = tid + it * 512;
            int q = idx & 127, cl = idx >> 7;
            size_t gi = (size_t)(b * CIN_ + 64 * blk + cl) * NPT + n0 + q;
            out[gi] = sT[cl * 132 + q] + gin[gi];
        }
        __syncthreads();
    }
}

// ================= launch =================
extern "C" void kernel_launch(void* const* d_in, const int* in_sizes, int n_in,
                              void* d_out, int out_size)
{
    const float* x     = (const float*)d_in[0];
    const float* g     = (const float*)d_in[1];
    const float* Wq    = (const float*)d_in[2];
    const float* bq    = (const float*)d_in[3];
    const float* Wk    = (const float*)d_in[4];
    const float* bk    = (const float*)d_in[5];
    const float* Wv    = (const float*)d_in[6];
    const float* bv    = (const float*)d_in[7];
    const float* gamma = (const float*)d_in[8];
    float* out = (float*)d_out;
    (void)in_sizes; (void)n_in; (void)out_size;

    cudaFuncSetAttribute(attn_tc, cudaFuncAttributeMaxDynamicSharedMemorySize, SMEM_TOTAL);
    cudaFuncSetAttribute(proj_mma, cudaFuncAttributeMaxDynamicSharedMemorySize, PROJ_SMEM);

    conv_w <<<512, 256>>>(Wq, Wk, Wv);
    conv_xg<<<dim3(NPT / 32, CIN_ / 32, 8), 256>>>(x, g);
    proj_mma<<<dim3(NPT / 128, 8, BSZ), 256, PROJ_SMEM>>>(bq, bk, bv);
    attn_tc<<<dim3(NPT / QT, BSZ), 512, SMEM_TOTAL>>>(g, gamma, out);
}

// round 14
// speedup vs baseline: 2.9458x; 1.0953x over previous
#include <cuda_runtime.h>
#include <cuda_bf16.h>
#include <cuda_fp16.h>
#include <cstdint>

#define BSZ 4
#define CIN_ 256
#define CQK_ 128
#define NPT 4096
#define KT 64            // keys per tile (attention)
#define NT 64            // tiles
#define QT 128           // queries per CTA

// scratch (device globals; no allocation allowed)
__device__ __half g_qh[BSZ * NPT * CQK_];          // [b][n][o] fp16
__device__ __half g_kh[BSZ * NPT * CQK_];          // [b][m][o] fp16
__device__ __nv_bfloat16 g_vh[BSZ * CIN_ * NPT];   // [b][c][m] bf16 channel-major
// projection inputs, bf16 hi/lo, transposed to [b][n][c]
__device__ __nv_bfloat16 g_xh[BSZ * NPT * CIN_];
__device__ __nv_bfloat16 g_xl[BSZ * NPT * CIN_];
__device__ __nv_bfloat16 g_gh[BSZ * NPT * CIN_];
__device__ __nv_bfloat16 g_gl[BSZ * NPT * CIN_];
// weights bf16 hi/lo, [o 0..511][c] (Q rows 0-127, K 128-255, V 256-511)
__device__ __nv_bfloat16 g_wh[512 * CIN_];
__device__ __nv_bfloat16 g_wl[512 * CIN_];

// ================= helpers =================
__device__ __forceinline__ uint32_t smem_u32(const void* p) {
    uint32_t a;
    asm("{ .reg .u64 t; cvta.to.shared.u64 t, %1; cvt.u32.u64 %0, t; }" : "=r"(a) : "l"(p));
    return a;
}
__device__ __forceinline__ void cp_async16(uint32_t dst, const void* src) {
    asm volatile("cp.async.cg.shared.global [%0], [%1], 16;" :: "r"(dst), "l"(src) : "memory");
}
#define CP_COMMIT() asm volatile("cp.async.commit_group;" ::: "memory")
#define CP_WAIT0()  asm volatile("cp.async.wait_group 0;" ::: "memory")

__device__ __forceinline__ void ldsm4(uint32_t addr, uint32_t r[4]) {
    asm volatile("ldmatrix.sync.aligned.m8n8.x4.shared.b16 {%0,%1,%2,%3}, [%4];"
        : "=r"(r[0]), "=r"(r[1]), "=r"(r[2]), "=r"(r[3]) : "r"(addr));
}
__device__ __forceinline__ void mma_f16(float c[4], const uint32_t a[4],
                                        uint32_t b0, uint32_t b1) {
    asm("mma.sync.aligned.m16n8k16.row.col.f32.f16.f16.f32 "
        "{%0,%1,%2,%3}, {%4,%5,%6,%7}, {%8,%9}, {%0,%1,%2,%3};"
        : "+f"(c[0]), "+f"(c[1]), "+f"(c[2]), "+f"(c[3])
        : "r"(a[0]), "r"(a[1]), "r"(a[2]), "r"(a[3]), "r"(b0), "r"(b1));
}
__device__ __forceinline__ void mma_bf16(float c[4], const uint32_t a[4],
                                         uint32_t b0, uint32_t b1) {
    asm("mma.sync.aligned.m16n8k16.row.col.f32.bf16.bf16.f32 "
        "{%0,%1,%2,%3}, {%4,%5,%6,%7}, {%8,%9}, {%0,%1,%2,%3};"
        : "+f"(c[0]), "+f"(c[1]), "+f"(c[2]), "+f"(c[3])
        : "r"(a[0]), "r"(a[1]), "r"(a[2]), "r"(a[3]), "r"(b0), "r"(b1));
}

// 256B-row swizzle (Q, K in attention)
__device__ __forceinline__ uint32_t sw256(int r, int byte) {
    return (uint32_t)(r * 256 + (((byte >> 4) ^ (r & 7)) << 4) + (byte & 15));
}
// 128B-row swizzle (V, proj tiles)
__device__ __forceinline__ uint32_t sw128(int r, int byte) {
    return (uint32_t)(r * 128 + (((byte >> 4) ^ (r & 7)) << 4) + (byte & 15));
}

__device__ __forceinline__ uint32_t h2u(float a, float b) {
    __half2 h = __floats2half2_rn(a, b);
    return *(uint32_t*)&h;
}
__device__ __forceinline__ uint32_t b2u(float a, float b) {
    __nv_bfloat162 h = __floats2bfloat162_rn(a, b);
    return *(uint32_t*)&h;
}

extern __shared__ __align__(16) char smem[];

// ================= conversion kernels =================
__global__ __launch_bounds__(256)
void conv_w(const float* __restrict__ Wq, const float* __restrict__ Wk,
            const float* __restrict__ Wv)
{
    int idx = blockIdx.x * 256 + threadIdx.x;      // [0, 512*256)
    int o = idx >> 8, c = idx & 255;
    float v = (o < 128) ? Wq[o * 256 + c]
            : (o < 256) ? Wk[(o - 128) * 256 + c]
                        : Wv[(o - 256) * 256 + c];
    __nv_bfloat16 h = __float2bfloat16_rn(v);
    g_wh[idx] = h;
    g_wl[idx] = __float2bfloat16_rn(v - __bfloat162float(h));
}

__global__ __launch_bounds__(256)
void conv_xg(const float* __restrict__ x, const float* __restrict__ gg)
{
    __shared__ float s[32][33];
    const int tid = threadIdx.x;
    const int b = blockIdx.z & 3;
    const bool isx = blockIdx.z < 4;
    const float* src = (isx ? x : gg) + (size_t)b * CIN_ * NPT;
    __nv_bfloat16* dh = (isx ? g_xh : g_gh) + (size_t)b * NPT * CIN_;
    __nv_bfloat16* dl = (isx ? g_xl : g_gl) + (size_t)b * NPT * CIN_;
    const int n0 = blockIdx.x * 32, c0 = blockIdx.y * 32;
#pragma unroll
    for (int i = 0; i < 4; i++) {
        int idx = tid + i * 256;
        int c = idx >> 5, n = idx & 31;
        s[c][n] = src[(size_t)(c0 + c) * NPT + n0 + n];
    }
    __syncthreads();
#pragma unroll
    for (int i = 0; i < 2; i++) {
        int idx = tid + i * 256;
        int n = idx >> 4, cp = idx & 15;
        float v0 = s[2 * cp][n], v1 = s[2 * cp + 1][n];
        __nv_bfloat16 h0 = __float2bfloat16_rn(v0), h1 = __float2bfloat16_rn(v1);
        size_t o = (size_t)(n0 + n) * CIN_ + c0 + 2 * cp;
        *(uint32_t*)&dh[o] = (uint32_t)__bfloat16_as_ushort(h0) |
                             ((uint32_t)__bfloat16_as_ushort(h1) << 16);
        *(uint32_t*)&dl[o] = b2u(v0 - __bfloat162float(h0), v1 - __bfloat162float(h1));
    }
}

// ================= tensor-core projection GEMM =================
// C[n, o] = sum_c X[n,c]*W[o,c] + bias[o], 3-pass bf16 split (fp32-accurate).
#define PSTAGE 49152u        // { Ah 16K | Al 16K | Bh 8K | Bl 8K }
#define PBIAS  98304u
#define PROJ_SMEM 98560

__device__ __forceinline__ void load_pstage(uint32_t sb, int stage, int ct, int tid,
    const __nv_bfloat16* ah, const __nv_bfloat16* al, int b, int n0, int o0)
{
    uint32_t stg = sb + (uint32_t)stage * PSTAGE;
#pragma unroll
    for (int i = 0; i < 12; i++) {
        int c = tid + i * 256;                       // 3072 chunks of 16B
        if (c < 2048) {                              // A hi/lo: 128 rows x 128B
            const __nv_bfloat16* s = (c < 1024) ? ah : al;
            int cc = c & 1023;
            int r = cc >> 3, ch = cc & 7;
            const __nv_bfloat16* src = s + (size_t)(b * NPT + n0 + r) * CIN_ + ct * 64 + ch * 8;
            cp_async16(stg + ((c < 1024) ? 0u : 16384u) + sw128(r, ch * 16), src);
        } else {                                     // B hi/lo: 64 rows x 128B
            const __nv_bfloat16* s = (c < 2560) ? g_wh : g_wl;
            int cc = c & 511;
            int r = cc >> 3, ch = cc & 7;
            const __nv_bfloat16* src = s + (size_t)(o0 + r) * CIN_ + ct * 64 + ch * 8;
            cp_async16(stg + ((c < 2560) ? 32768u : 40960u) + sw128(r, ch * 16), src);
        }
    }
}

__global__ __launch_bounds__(256)
void proj_mma(const float* __restrict__ bq, const float* __restrict__ bk,
              const float* __restrict__ bv)
{
    const uint32_t sb = smem_u32(smem);
    const int tid = threadIdx.x;
    const int lane = tid & 31, wid = tid >> 5;
    const int g = lane >> 2, tig = lane & 3;
    const int r0 = wid * 16;
    const int b  = blockIdx.z;
    const int n0 = blockIdx.x * 128;
    const int oy = blockIdx.y;
    const int o0 = oy * 64;
    const int dstT = (oy < 2) ? 0 : (oy < 4) ? 1 : 2;   // Q / K / V

    const __nv_bfloat16* ah = (dstT == 0) ? g_xh : g_gh;
    const __nv_bfloat16* al = (dstT == 0) ? g_xl : g_gl;
    const float* biasp = (dstT == 0) ? (bq + o0) : (dstT == 1) ? (bk + o0 - 128) : (bv + o0 - 256);

    float* sBias = (float*)(smem + PBIAS);
    if (tid < 64) sBias[tid] = biasp[tid];

    load_pstage(sb, 0, 0, tid, ah, al, b, n0, o0);
    CP_COMMIT();

    float accC[8][4];
#pragma unroll
    for (int j = 0; j < 8; j++)
#pragma unroll
        for (int q = 0; q < 4; q++) accC[j][q] = 0.0f;

    for (int ct = 0; ct < 4; ct++) {
        CP_WAIT0();
        __syncthreads();
        if (ct < 3) { load_pstage(sb, (ct + 1) & 1, ct + 1, tid, ah, al, b, n0, o0); CP_COMMIT(); }

        const uint32_t stg = sb + (uint32_t)(ct & 1) * PSTAGE;
#pragma unroll
        for (int kk = 0; kk < 4; kk++) {
            uint32_t Ah[4], Al[4];
            {
                int rr = r0 + (lane & 15);
                int byte = kk * 32 + ((lane >> 4) & 1) * 16;
                ldsm4(stg + sw128(rr, byte), Ah);
                ldsm4(stg + 16384u + sw128(rr, byte), Al);
            }
#pragma unroll
            for (int jb = 0; jb < 4; jb++) {
                int rr = jb * 16 + ((lane >> 4) << 3) + (lane & 7);
                int byte = kk * 32 + ((lane >> 3) & 1) * 16;
                uint32_t Bh[4], Bl[4];
                ldsm4(stg + 32768u + sw128(rr, byte), Bh);
                ldsm4(stg + 40960u + sw128(rr, byte), Bl);
                mma_bf16(accC[2*jb],   Ah, Bh[0], Bh[1]);
                mma_bf16(accC[2*jb+1], Ah, Bh[2], Bh[3]);
                mma_bf16(accC[2*jb],   Al, Bh[0], Bh[1]);
                mma_bf16(accC[2*jb+1], Al, Bh[2], Bh[3]);
                mma_bf16(accC[2*jb],   Ah, Bl[0], Bl[1]);
                mma_bf16(accC[2*jb+1], Ah, Bl[2], Bl[3]);
            }
        }
    }
    __syncthreads();

    if (dstT < 2) {      // Q / K: [b][n][o] fp16
        __half* dst = (dstT == 0) ? g_qh : g_kh;
        int og = (dstT == 0) ? o0 : (o0 - 128);
#pragma unroll
        for (int jb = 0; jb < 4; jb++)
#pragma unroll
            for (int hb = 0; hb < 2; hb++) {
                int ol = jb * 16 + hb * 8 + 2 * tig;
                float b0 = sBias[ol], b1 = sBias[ol + 1];
                float* a = accC[2 * jb + hb];
                size_t i0 = (size_t)(b * NPT + n0 + r0 + g) * CQK_ + og + ol;
                size_t i1 = i0 + (size_t)8 * CQK_;
                *(uint32_t*)&dst[i0] = h2u(a[0] + b0, a[1] + b1);
                *(uint32_t*)&dst[i1] = h2u(a[2] + b0, a[3] + b1);
            }
    } else {             // V: transpose to [b][c][m] bf16 via smem
        __nv_bfloat16* sT = (__nv_bfloat16*)smem;    // [64][130]
#pragma unroll
        for (int jb = 0; jb < 4; jb++)
#pragma unroll
            for (int hb = 0; hb < 2; hb++) {
                int ol = jb * 16 + hb * 8 + 2 * tig;
                float b0 = sBias[ol], b1 = sBias[ol + 1];
                float* a = accC[2 * jb + hb];
                sT[(ol    ) * 130 + r0 + g]     = __float2bfloat16_rn(a[0] + b0);
                sT[(ol + 1) * 130 + r0 + g]     = __float2bfloat16_rn(a[1] + b1);
                sT[(ol    ) * 130 + r0 + g + 8] = __float2bfloat16_rn(a[2] + b0);
                sT[(ol + 1) * 130 + r0 + g + 8] = __float2bfloat16_rn(a[3] + b1);
            }
        __syncthreads();
#pragma unroll
        for (int i = 0; i < 16; i++) {
            int w = tid + i * 256;
            int o = w >> 6, nn = (w & 63) * 2;
            uint32_t val = *(uint32_t*)&sT[o * 130 + nn];
            *(uint32_t*)&g_vh[(size_t)(b * CIN_ + (o0 - 256) + o) * NPT + n0 + nn] = val;
        }
    }
}

// ================= Fused mma.sync flash attention (1-pass fp16 S / bf16 PV) =================
#define SM_QH   0u           // Q fp16: 128 rows x 256B = 32K
#define SM_ST0  32768u       // stage: { Kh 16K | V 32K } = 48K, x2
#define STAGESZ 49152u
#define SM_P    131072u      // per-warp P fragment regions: 16 x 1KB
#define SM_MAX  147456u      // [128][2] f32
#define SM_L    148480u      // [128][2] f32
#define SMEM_TOTAL 149504

__device__ __forceinline__ void load_stage(uint32_t sb, int stage, int m0, int tid,
    const __half* kh, const __nv_bfloat16* vh)
{
    uint32_t stg = sb + SM_ST0 + (uint32_t)stage * STAGESZ;
#pragma unroll
    for (int i = 0; i < 6; i++) {
        int c = tid + i * 512;                       // 3072 chunks of 16B
        if (c < 1024) {                              // Kh: 64 rows x 256B
            int r = c >> 4, ch = c & 15;
            const __half* src = kh + (size_t)(m0 + r) * CQK_ + ch * 8;
            cp_async16(stg + sw256(r, ch * 16), src);
        } else {                                     // V: 256 ch x 128B
            int cc = c - 1024;
            int r = cc >> 3, ch = cc & 7;            // r = channel
            const __nv_bfloat16* src = vh + (size_t)r * NPT + m0 + ch * 8;
            cp_async16(stg + 16384u + sw128(r, ch * 16), src);
        }
    }
}

__global__ __launch_bounds__(512, 1)
void attn_tc(const float* __restrict__ gin, const float* __restrict__ gamma_p,
             float* __restrict__ out)
{
    const uint32_t sb = smem_u32(smem);
    const int tid  = threadIdx.x;
    const int lane = tid & 31, wid = tid >> 5;
    const int wq = wid & 7, wh = wid >> 3;
    const int g = lane >> 2, tig = lane & 3;
    const int r0 = 16 * wq;
    const int b  = blockIdx.y;
    const int n0 = blockIdx.x * QT;

    const __half* qh = g_qh + (size_t)(b * NPT + n0) * CQK_;
    const __half* kh = g_kh + (size_t)b * NPT * CQK_;
    const __nv_bfloat16* vh = g_vh + (size_t)b * CIN_ * NPT;

    const uint32_t pOwn  = sb + SM_P + (uint32_t)((wq * 2 + wh) * 1024) + (uint32_t)(lane * 4);
    const uint32_t pPeer = sb + SM_P + (uint32_t)((wq * 2 + (1 - wh)) * 1024) + (uint32_t)(lane * 4);

    // prologue: Q + stage0
#pragma unroll
    for (int i = 0; i < 4; i++) {
        int c = tid + i * 512;                       // 2048 chunks
        int r = c >> 4, ch = c & 15;
        const __half* src = qh + (size_t)r * CQK_ + ch * 8;
        cp_async16(sb + SM_QH + sw256(r, ch * 16), src);
    }
    load_stage(sb, 0, 0, tid, kh, vh);
    CP_COMMIT();

    float accO[16][4];
#pragma unroll
    for (int j = 0; j < 16; j++)
#pragma unroll
        for (int q = 0; q < 4; q++) accO[j][q] = 0.0f;

    float lsum0 = 0.0f, lsum1 = 0.0f;
    float m0r = 0.0f, m1r = 0.0f;
    const int n0w = 32 * wh;

    for (int t = 0; t < NT; t++) {
        CP_WAIT0();
        __syncthreads();
        if (t + 1 < NT) { load_stage(sb, (t + 1) & 1, (t + 1) * KT, tid, kh, vh); CP_COMMIT(); }

        const uint32_t stg = sb + SM_ST0 + (uint32_t)(t & 1) * STAGESZ;
        const uint32_t sKh = stg, sV = stg + 16384u;

        // ---- S = Q·K  (16 rows x 32 keys per warp, fp16 1-pass) ----
        float accS[4][4];
#pragma unroll
        for (int j = 0; j < 4; j++)
#pragma unroll
            for (int q = 0; q < 4; q++) accS[j][q] = 0.0f;

#pragma unroll
        for (int kk = 0; kk < 8; kk++) {
            uint32_t Ah[4];
            {
                int rr = r0 + (lane & 15);
                int byte = kk * 32 + ((lane >> 4) & 1) * 16;
                ldsm4(sb + SM_QH + sw256(rr, byte), Ah);
            }
#pragma unroll
            for (int jp = 0; jp < 2; jp++) {
                int rr = n0w + 16 * jp + ((lane >> 4) << 3) + (lane & 7);
                int byte = kk * 32 + ((lane >> 3) & 1) * 16;
                uint32_t Bh[4];
                ldsm4(sKh + sw256(rr, byte), Bh);
                mma_f16(accS[2*jp],   Ah, Bh[0], Bh[1]);
                mma_f16(accS[2*jp+1], Ah, Bh[2], Bh[3]);
            }
        }

        // ---- fixed row max from tile 0 ----
        if (t == 0) {
            float mA = fmaxf(fmaxf(accS[0][0], accS[0][1]), fmaxf(accS[1][0], accS[1][1]));
            mA = fmaxf(mA, fmaxf(fmaxf(accS[2][0], accS[2][1]), fmaxf(accS[3][0], accS[3][1])));
            float mB = fmaxf(fmaxf(accS[0][2], accS[0][3]), fmaxf(accS[1][2], accS[1][3]));
            mB = fmaxf(mB, fmaxf(fmaxf(accS[2][2], accS[2][3]), fmaxf(accS[3][2], accS[3][3])));
            mA = fmaxf(mA, __shfl_xor_sync(0xffffffffu, mA, 1));
            mA = fmaxf(mA, __shfl_xor_sync(0xffffffffu, mA, 2));
            mB = fmaxf(mB, __shfl_xor_sync(0xffffffffu, mB, 1));
            mB = fmaxf(mB, __shfl_xor_sync(0xffffffffu, mB, 2));
            float* sM = (float*)(smem + SM_MAX);
            if (tig == 0) {
                sM[(r0 + g) * 2 + wh]     = mA;
                sM[(r0 + g + 8) * 2 + wh] = mB;
            }
            __syncthreads();
            m0r = fmaxf(sM[(r0 + g) * 2],     sM[(r0 + g) * 2 + 1]);
            m1r = fmaxf(sM[(r0 + g + 8) * 2], sM[(r0 + g + 8) * 2 + 1]);
        }

        // ---- softmax: accS -> bf16 A-fragments in registers; l from rounded P ----
        uint32_t aP[2][4];
#pragma unroll
        for (int j = 0; j < 4; j++) {
            float e0 = __expf(accS[j][0] - m0r);
            float e1 = __expf(accS[j][1] - m0r);
            float e2 = __expf(accS[j][2] - m1r);
            float e3 = __expf(accS[j][3] - m1r);
            __nv_bfloat162 p01 = __floats2bfloat162_rn(e0, e1);
            __nv_bfloat162 p23 = __floats2bfloat162_rn(e2, e3);
            lsum0 += __bfloat162float(p01.x) + __bfloat162float(p01.y);
            lsum1 += __bfloat162float(p23.x) + __bfloat162float(p23.y);
            aP[j >> 1][((j & 1) << 1)]     = *(uint32_t*)&p01;
            aP[j >> 1][((j & 1) << 1) | 1] = *(uint32_t*)&p23;
        }

#pragma unroll
        for (int i = 0; i < 8; i++)
            *(uint32_t*)(smem + (pOwn - sb) + (uint32_t)(i * 128)) = aP[i >> 2][i & 3];

        // ---- PV own key-chunks first ----
#pragma unroll
        for (int cc = 0; cc < 2; cc++) {
            const int kk = 2 * wh + cc;
#pragma unroll
            for (int jp = 0; jp < 8; jp++) {
                int rr = 128 * wh + 16 * jp + ((lane >> 4) << 3) + (lane & 7);
                int byte = kk * 32 + ((lane >> 3) & 1) * 16;
                uint32_t Bv[4];
                ldsm4(sV + sw128(rr, byte), Bv);
                mma_bf16(accO[2*jp],   aP[cc], Bv[0], Bv[1]);
                mma_bf16(accO[2*jp+1], aP[cc], Bv[2], Bv[3]);
            }
        }

        asm volatile("bar.sync %0, %1;" :: "r"(1 + wq), "r"(64) : "memory");

        uint32_t aQ[2][4];
#pragma unroll
        for (int i = 0; i < 8; i++)
            aQ[i >> 2][i & 3] = *(const uint32_t*)(smem + (pPeer - sb) + (uint32_t)(i * 128));

        // ---- PV partner key-chunks ----
#pragma unroll
        for (int cc = 0; cc < 2; cc++) {
            const int kk = 2 * (1 - wh) + cc;
#pragma unroll
            for (int jp = 0; jp < 8; jp++) {
                int rr = 128 * wh + 16 * jp + ((lane >> 4) << 3) + (lane & 7);
                int byte = kk * 32 + ((lane >> 3) & 1) * 16;
                uint32_t Bv[4];
                ldsm4(sV + sw128(rr, byte), Bv);
                mma_bf16(accO[2*jp],   aQ[cc], Bv[0], Bv[1]);
                mma_bf16(accO[2*jp+1], aQ[cc], Bv[2], Bv[3]);
            }
        }
    }

    // ---- l reduction ----
    lsum0 += __shfl_xor_sync(0xffffffffu, lsum0, 1);
    lsum0 += __shfl_xor_sync(0xffffffffu, lsum0, 2);
    lsum1 += __shfl_xor_sync(0xffffffffu, lsum1, 1);
    lsum1 += __shfl_xor_sync(0xffffffffu, lsum1, 2);
    float* sL = (float*)(smem + SM_L);
    if (tig == 0) {
        sL[(r0 + g) * 2 + wh]     = lsum0;
        sL[(r0 + g + 8) * 2 + wh] = lsum1;
    }
    __syncthreads();
    const float rl0 = 1.0f / (sL[(r0 + g) * 2]     + sL[(r0 + g) * 2 + 1]);
    const float rl1 = 1.0f / (sL[(r0 + g + 8) * 2] + sL[(r0 + g + 8) * 2 + 1]);
    const float gam = gamma_p[0];

    // ---- epilogue: smem transpose, coalesced  out = gamma*O/l + g ----
    float* sT = (float*)(smem + SM_ST0);         // [64 ch][128 q] pad-132
#pragma unroll 1
    for (int blk = 0; blk < 4; blk++) {
        if (wh == (blk >> 1)) {
#pragma unroll
            for (int jj = 0; jj < 8; jj++) {
                int j  = 8 * (blk & 1) + jj;
                int cl = 8 * jj + 2 * tig;
                sT[(cl    ) * 132 + r0 + g]     = gam * accO[j][0] * rl0;
                sT[(cl + 1) * 132 + r0 + g]     = gam * accO[j][1] * rl0;
                sT[(cl    ) * 132 + r0 + g + 8] = gam * accO[j][2] * rl1;
                sT[(cl + 1) * 132 + r0 + g + 8] = gam * accO[j][3] * rl1;
            }
        }
        __syncthreads();
#pragma unroll
        for (int it = 0; it < 16; it++) {
            int idx = tid + it * 512;
            int q = idx & 127, cl = idx >> 7;
            size_t gi = (size_t)(b * CIN_ + 64 * blk + cl) * NPT + n0 + q;
            out[gi] = sT[cl * 132 + q] + gin[gi];
        }
        __syncthreads();
    }
}

// ================= launch =================
extern "C" void kernel_launch(void* const* d_in, const int* in_sizes, int n_in,
                              void* d_out, int out_size)
{
    const float* x     = (const float*)d_in[0];
    const float* g     = (const float*)d_in[1];
    const float* Wq    = (const float*)d_in[2];
    const float* bq    = (const float*)d_in[3];
    const float* Wk    = (const float*)d_in[4];
    const float* bk    = (const float*)d_in[5];
    const float* Wv    = (const float*)d_in[6];
    const float* bv    = (const float*)d_in[7];
    const float* gamma = (const float*)d_in[8];
    float* out = (float*)d_out;
    (void)in_sizes; (void)n_in; (void)out_size;

    cudaFuncSetAttribute(attn_tc, cudaFuncAttributeMaxDynamicSharedMemorySize, SMEM_TOTAL);
    cudaFuncSetAttribute(proj_mma, cudaFuncAttributeMaxDynamicSharedMemorySize, PROJ_SMEM);

    conv_w <<<512, 256>>>(Wq, Wk, Wv);
    conv_xg<<<dim3(NPT / 32, CIN_ / 32, 8), 256>>>(x, g);
    proj_mma<<<dim3(NPT / 128, 8, BSZ), 256, PROJ_SMEM>>>(bq, bk, bv);
    attn_tc<<<dim3(NPT / QT, BSZ), 512, SMEM_TOTAL>>>(g, gamma, out);
}